// round 9
// baseline (speedup 1.0000x reference)
#include <cuda_runtime.h>
#include <cuda_fp16.h>
#include <cstdint>
#include <math.h>
#include <float.h>

constexpr int Hh = 8;
constexpr int Jn = 22;
constexpr int Sn = 66;
#define NEGV (-9e15f)

// ---------------- smem byte layout ----------------
constexpr int XH_OFF  = 0;        // x hi: 66 x 264 halfs
constexpr int XL_OFF  = 34848;    // x lo
constexpr int WH_OFF  = 69696;    // W hi: 96 x 264 halfs
constexpr int WL_OFF  = 120384;   // W lo
constexpr int QH_OFF  = 171072;   // q hi: 66 x 36 halfs (72B rows)
constexpr int QL_OFF  = 175824;
constexpr int KH_OFF  = 180576;   // k hi: 66 x 36 halfs (scores B layout)
constexpr int KL_OFF  = 185328;
constexpr int VTH_OFF = 190080;   // v^T hi: 32 x 72 halfs (144B rows)
constexpr int VTL_OFF = 194688;
constexpr int VTAIL_OFF = 199296; // V rows 64,65 fp32: 2 x 32 floats
constexpr int PP_OFF  = 199552;   // pp fp32 66 x 72
constexpr int OO_OFF  = 218560;   // oo fp32 66 x 33
constexpr int BIAS_OFF= 227272;   // 96 floats
constexpr int SMEM_BYTES = 227656;

constexpr int PP_STRIDE = 72, OO_STRIDE = 33;

typedef unsigned long long ull;

// pre-split weights in global, [h][n][k] layout, scaled x16
__device__ __align__(16) __half g_Wh[8 * 96 * 256];
__device__ __align__(16) __half g_Wl[8 * 96 * 256];

__global__ void repack_weights(const float* __restrict__ Wq,
                               const float* __restrict__ Wk,
                               const float* __restrict__ Wv) {
    int i = blockIdx.x * blockDim.x + threadIdx.x;
    if (i >= 8 * 96 * 256) return;
    int k = i & 255;
    int n = (i >> 8) % 96;
    int h = i / (96 * 256);
    const float* Wsrc = (n < 32) ? Wq : (n < 64 ? Wk : Wv);
    float w = 16.0f * Wsrc[(h * 32 + (n & 31)) * 256 + k];
    __half hi = __float2half_rn(w);
    __half lo = __float2half_rn(w - __half2float(hi));
    g_Wh[i] = hi;
    g_Wl[i] = lo;
}

// ---------------- device helpers ----------------
static __device__ __forceinline__ void cp16(unsigned dst, const void* src) {
    asm volatile("cp.async.ca.shared.global [%0], [%1], 16;" :: "r"(dst), "l"(src));
}
static __device__ __forceinline__ void cp_commit() { asm volatile("cp.async.commit_group;"); }
static __device__ __forceinline__ void cp_wait0()  { asm volatile("cp.async.wait_group 0;"); }

static __device__ __forceinline__ void mma16816(float* c, const unsigned* a, const unsigned* b) {
    asm volatile("mma.sync.aligned.m16n8k16.row.col.f32.f16.f16.f32 "
        "{%0,%1,%2,%3}, {%4,%5,%6,%7}, {%8,%9}, {%0,%1,%2,%3};"
        : "+f"(c[0]), "+f"(c[1]), "+f"(c[2]), "+f"(c[3])
        : "r"(a[0]), "r"(a[1]), "r"(a[2]), "r"(a[3]), "r"(b[0]), "r"(b[1]));
}

// fp32 pair -> (hi f16x2, lo f16x2)
static __device__ __forceinline__ void cvt_split(float2 f, unsigned &hi, unsigned &lo) {
    __half2 h2 = __float22half2_rn(f);
    float2 hf = __half22float2(h2);
    __half2 l2 = __float22half2_rn(make_float2(f.x - hf.x, f.y - hf.y));
    hi = *reinterpret_cast<unsigned*>(&h2);
    lo = *reinterpret_cast<unsigned*>(&l2);
}

__global__ __launch_bounds__(512, 1)
void mha_fused_kernel(const float* __restrict__ x,
                      const float* __restrict__ bq,
                      const float* __restrict__ bk,
                      const float* __restrict__ bv,
                      const float* __restrict__ Wc, const float* __restrict__ bc,
                      float* __restrict__ out)
{
    extern __shared__ float sm[];
    char* smc = reinterpret_cast<char*>(sm);
    float* vtail   = reinterpret_cast<float*>(smc + VTAIL_OFF);
    float* pp      = reinterpret_cast<float*>(smc + PP_OFF);
    float* oo      = reinterpret_cast<float*>(smc + OO_OFF);
    float* biasArr = reinterpret_cast<float*>(smc + BIAS_OFF);

    const int bt   = blockIdx.x;
    const int tid  = threadIdx.x;
    const int lane = tid & 31;
    const int wid  = tid >> 5;

    const unsigned sbase = (unsigned)__cvta_generic_to_shared(smc);

    // ---- prologue: stage W(0) via cp.async ----
    {
        const char* srcH = reinterpret_cast<const char*>(g_Wh);
        const char* srcL = reinterpret_cast<const char*>(g_Wl);
        for (int c = tid; c < 6144; c += 512) {
            int half_sel = c >= 3072;
            int cc = c - (half_sel ? 3072 : 0);
            int n = cc >> 5, ch = cc & 31;
            const char* s = (half_sel ? srcL : srcH) + n * 512 + ch * 16;
            unsigned d = sbase + (half_sel ? WL_OFF : WH_OFF) + n * 528 + ch * 16;
            cp16(d, s);
        }
        cp_commit();
    }
    // ---- x fp32 -> fp16 hi/lo split ----
    {
        const float* xg = x + (size_t)bt * (Sn * 256);
        for (int t = tid; t < Sn * 256; t += 512) {
            int r = t >> 8, k = t & 255;
            float xv = xg[t];
            __half hi = __float2half_rn(xv);
            __half lo = __float2half_rn(xv - __half2float(hi));
            *reinterpret_cast<__half*>(smc + XH_OFF + r * 528 + k * 2) = hi;
            *reinterpret_cast<__half*>(smc + XL_OFF + r * 528 + k * 2) = lo;
        }
    }

    const float scale = 0.17677669529663687f; // 1/sqrt(32)

    for (int h = 0; h < Hh; ++h) {
        cp_wait0();
        if (tid < 96) {
            const float* bsrc = (tid < 32) ? bq : (tid < 64 ? bk : bv);
            biasArr[tid] = bsrc[h * 32 + (tid & 31)];
        }
        __syncthreads();

        // ================= QKV projection (HMMA, fp16 2-term split) =================
        for (int t = wid; t < 20; t += 16) {
            int mt = t >> 2, nt = t & 3;
            int m0 = mt * 16, n0 = nt * 24;
            int g = lane >> 2, kq = (lane & 3) * 2;
            int r0 = m0 + g, r1 = r0 + 8;
            int r0c = (r0 < 66) ? r0 : 65;
            int r1c = (r1 < 66) ? r1 : 65;
            const char* xh0 = smc + XH_OFF + r0c * 528;
            const char* xh1 = smc + XH_OFF + r1c * 528;
            const char* xl0 = smc + XL_OFF + r0c * 528;
            const char* xl1 = smc + XL_OFF + r1c * 528;
            const char* wh0 = smc + WH_OFF + (n0 + g) * 528;
            const char* wh1 = wh0 + 8 * 528;
            const char* wh2 = wh0 + 16 * 528;
            const char* wl0 = smc + WL_OFF + (n0 + g) * 528;
            const char* wl1 = wl0 + 8 * 528;
            const char* wl2 = wl0 + 16 * 528;

            float acc[3][4];
            #pragma unroll
            for (int j = 0; j < 3; ++j)
                #pragma unroll
                for (int e = 0; e < 4; ++e) acc[j][e] = 0.0f;

            #pragma unroll
            for (int ks = 0; ks < 16; ++ks) {
                int off = (ks * 16 + kq) * 2;
                unsigned a[4], al[4];
                a[0]  = *reinterpret_cast<const unsigned*>(xh0 + off);
                a[1]  = *reinterpret_cast<const unsigned*>(xh1 + off);
                a[2]  = *reinterpret_cast<const unsigned*>(xh0 + off + 16);
                a[3]  = *reinterpret_cast<const unsigned*>(xh1 + off + 16);
                al[0] = *reinterpret_cast<const unsigned*>(xl0 + off);
                al[1] = *reinterpret_cast<const unsigned*>(xl1 + off);
                al[2] = *reinterpret_cast<const unsigned*>(xl0 + off + 16);
                al[3] = *reinterpret_cast<const unsigned*>(xl1 + off + 16);

                unsigned b[2], bl[2];
                b[0]  = *reinterpret_cast<const unsigned*>(wh0 + off);
                b[1]  = *reinterpret_cast<const unsigned*>(wh0 + off + 16);
                bl[0] = *reinterpret_cast<const unsigned*>(wl0 + off);
                bl[1] = *reinterpret_cast<const unsigned*>(wl0 + off + 16);
                mma16816(acc[0], a, b);
                mma16816(acc[0], a, bl);
                mma16816(acc[0], al, b);

                b[0]  = *reinterpret_cast<const unsigned*>(wh1 + off);
                b[1]  = *reinterpret_cast<const unsigned*>(wh1 + off + 16);
                bl[0] = *reinterpret_cast<const unsigned*>(wl1 + off);
                bl[1] = *reinterpret_cast<const unsigned*>(wl1 + off + 16);
                mma16816(acc[1], a, b);
                mma16816(acc[1], a, bl);
                mma16816(acc[1], al, b);

                b[0]  = *reinterpret_cast<const unsigned*>(wh2 + off);
                b[1]  = *reinterpret_cast<const unsigned*>(wh2 + off + 16);
                bl[0] = *reinterpret_cast<const unsigned*>(wl2 + off);
                bl[1] = *reinterpret_cast<const unsigned*>(wl2 + off + 16);
                mma16816(acc[2], a, b);
                mma16816(acc[2], a, bl);
                mma16816(acc[2], al, b);
            }

            // epilogue: x1/16, +bias, relu(v); emit fp16 hi/lo tiles + V tail fp32
            #pragma unroll
            for (int j = 0; j < 3; ++j) {
                int cb = n0 + 8 * j + kq;
                #pragma unroll
                for (int e = 0; e < 2; ++e) {
                    int col = cb + e;
                    float bb = biasArr[col];
                    float v0 = acc[j][e]     * 0.0625f + bb;
                    float v1 = acc[j][2 + e] * 0.0625f + bb;
                    if (col >= 64) { v0 = fmaxf(v0, 0.0f); v1 = fmaxf(v1, 0.0f); }
                    __half h0 = __float2half_rn(v0);
                    __half l0 = __float2half_rn(v0 - __half2float(h0));
                    __half h1 = __float2half_rn(v1);
                    __half l1 = __float2half_rn(v1 - __half2float(h1));
                    if (col < 32) {
                        if (r0 < 66) {
                            *reinterpret_cast<__half*>(smc + QH_OFF + r0 * 72 + col * 2) = h0;
                            *reinterpret_cast<__half*>(smc + QL_OFF + r0 * 72 + col * 2) = l0;
                        }
                        if (r1 < 66) {
                            *reinterpret_cast<__half*>(smc + QH_OFF + r1 * 72 + col * 2) = h1;
                            *reinterpret_cast<__half*>(smc + QL_OFF + r1 * 72 + col * 2) = l1;
                        }
                    } else if (col < 64) {
                        int cc = col - 32;
                        if (r0 < 66) {
                            *reinterpret_cast<__half*>(smc + KH_OFF + r0 * 72 + cc * 2) = h0;
                            *reinterpret_cast<__half*>(smc + KL_OFF + r0 * 72 + cc * 2) = l0;
                        }
                        if (r1 < 66) {
                            *reinterpret_cast<__half*>(smc + KH_OFF + r1 * 72 + cc * 2) = h1;
                            *reinterpret_cast<__half*>(smc + KL_OFF + r1 * 72 + cc * 2) = l1;
                        }
                    } else {
                        int dd = col - 64;
                        if (r0 < 66) {
                            *reinterpret_cast<__half*>(smc + VTH_OFF + dd * 144 + r0 * 2) = h0;
                            *reinterpret_cast<__half*>(smc + VTL_OFF + dd * 144 + r0 * 2) = l0;
                            if (r0 >= 64) vtail[(r0 - 64) * 32 + dd] = v0;
                        }
                        if (r1 < 66) {
                            *reinterpret_cast<__half*>(smc + VTH_OFF + dd * 144 + r1 * 2) = h1;
                            *reinterpret_cast<__half*>(smc + VTL_OFF + dd * 144 + r1 * 2) = l1;
                            if (r1 >= 64) vtail[(r1 - 64) * 32 + dd] = v1;
                        }
                    }
                }
            }
        }
        __syncthreads();

        // ---- prefetch W(h+1), hidden behind attention phases ----
        if (h + 1 < Hh) {
            const char* srcH = reinterpret_cast<const char*>(g_Wh) + (size_t)(h + 1) * 49152;
            const char* srcL = reinterpret_cast<const char*>(g_Wl) + (size_t)(h + 1) * 49152;
            for (int c = tid; c < 6144; c += 512) {
                int half_sel = c >= 3072;
                int cc = c - (half_sel ? 3072 : 0);
                int n = cc >> 5, ch = cc & 31;
                const char* s = (half_sel ? srcL : srcH) + n * 512 + ch * 16;
                unsigned d = sbase + (half_sel ? WL_OFF : WH_OFF) + n * 528 + ch * 16;
                cp16(d, s);
            }
            cp_commit();
        }

        // ================= scores via HMMA: pp = mask(Q @ K^T) * scale =================
        for (int t = wid; t < 45; t += 16) {
            int mt = t / 9, nt = t - mt * 9;
            int m0 = mt * 16, n0 = nt * 8;
            int g = lane >> 2, kq = (lane & 3) * 2;
            int r0 = m0 + g, r1 = r0 + 8;
            int r0c = (r0 < 66) ? r0 : 65;
            int r1c = (r1 < 66) ? r1 : 65;
            int nr  = (n0 + g < 66) ? (n0 + g) : 65;
            const char* ah0 = smc + QH_OFF + r0c * 72;
            const char* ah1 = smc + QH_OFF + r1c * 72;
            const char* al0 = smc + QL_OFF + r0c * 72;
            const char* al1 = smc + QL_OFF + r1c * 72;
            const char* bh  = smc + KH_OFF + nr * 72;
            const char* blp = smc + KL_OFF + nr * 72;

            float acc[4] = {0.0f, 0.0f, 0.0f, 0.0f};
            #pragma unroll
            for (int ks = 0; ks < 2; ++ks) {
                int off = (ks * 16 + kq) * 2;
                unsigned a[4], al[4], b[2], bl[2];
                a[0]  = *reinterpret_cast<const unsigned*>(ah0 + off);
                a[1]  = *reinterpret_cast<const unsigned*>(ah1 + off);
                a[2]  = *reinterpret_cast<const unsigned*>(ah0 + off + 16);
                a[3]  = *reinterpret_cast<const unsigned*>(ah1 + off + 16);
                al[0] = *reinterpret_cast<const unsigned*>(al0 + off);
                al[1] = *reinterpret_cast<const unsigned*>(al1 + off);
                al[2] = *reinterpret_cast<const unsigned*>(al0 + off + 16);
                al[3] = *reinterpret_cast<const unsigned*>(al1 + off + 16);
                b[0]  = *reinterpret_cast<const unsigned*>(bh + off);
                b[1]  = *reinterpret_cast<const unsigned*>(bh + off + 16);
                bl[0] = *reinterpret_cast<const unsigned*>(blp + off);
                bl[1] = *reinterpret_cast<const unsigned*>(blp + off + 16);
                mma16816(acc, a, b);
                mma16816(acc, a, bl);
                mma16816(acc, al, b);
            }
            #pragma unroll
            for (int e = 0; e < 2; ++e) {
                int col = n0 + kq + e;
                bool mm0 = (r0 < Jn && col >= 2 * Jn) || (r0 >= 2 * Jn && col < Jn);
                bool mm1 = (r1 < Jn && col >= 2 * Jn) || (r1 >= 2 * Jn && col < Jn);
                float s0 = mm0 ? 0.0f : acc[e] * scale;
                float s1 = mm1 ? 0.0f : acc[2 + e] * scale;
                if (r0 < 66) pp[r0 * PP_STRIDE + col] = s0;
                if (r1 < 66) pp[r1 * PP_STRIDE + col] = s1;
            }
        }
        __syncthreads();

        // ================= softmax with threshold pruning =================
        for (int r = wid; r < Sn; r += 16) {
            float* row = pp + r * PP_STRIDE;
            float v0 = row[lane];
            float v1 = row[lane + 32];
            float v2 = (lane < 2) ? row[lane + 64] : -FLT_MAX;
            float m = fmaxf(fmaxf(v0, v1), v2);
            #pragma unroll
            for (int o = 16; o; o >>= 1) m = fmaxf(m, __shfl_xor_sync(0xffffffffu, m, o));
            float thr = m * (1.0f / 9.0f);
            float t0 = (fabsf(v0) <= thr) ? NEGV : v0;
            float t1 = (fabsf(v1) <= thr) ? NEGV : v1;
            float t2v = (lane < 2) ? ((fabsf(v2) <= thr) ? NEGV : v2) : -FLT_MAX;
            float M2 = fmaxf(fmaxf(t0, t1), t2v);
            #pragma unroll
            for (int o = 16; o; o >>= 1) M2 = fmaxf(M2, __shfl_xor_sync(0xffffffffu, M2, o));
            float e0 = __expf(t0 - M2);
            float e1 = __expf(t1 - M2);
            float e2 = (lane < 2) ? __expf(t2v - M2) : 0.0f;
            float s = e0 + e1 + e2;
            #pragma unroll
            for (int o = 16; o; o >>= 1) s += __shfl_xor_sync(0xffffffffu, s, o);
            float inv = 1.0f / s;
            row[lane]      = e0 * inv;
            row[lane + 32] = e1 * inv;
            if (lane < 2) row[lane + 64] = e2 * inv;
        }
        __syncthreads();

        // ================= P @ V via HMMA (in-flight fp16 split of P) =================
        for (int t = wid; t < 20; t += 16) {
            int mt = t >> 2, nt = t & 3;
            int m0 = mt * 16, n0 = nt * 8;
            int g = lane >> 2, kq = (lane & 3) * 2;
            int r0 = m0 + g, r1 = r0 + 8;
            int r0c = (r0 < 66) ? r0 : 65;
            int r1c = (r1 < 66) ? r1 : 65;
            const float* p0 = pp + r0c * PP_STRIDE;
            const float* p1 = pp + r1c * PP_STRIDE;
            const char* bh  = smc + VTH_OFF + (n0 + g) * 144;
            const char* blp = smc + VTL_OFF + (n0 + g) * 144;

            float acc[4] = {0.0f, 0.0f, 0.0f, 0.0f};
            #pragma unroll
            for (int ks = 0; ks < 4; ++ks) {
                int k0 = ks * 16 + kq;
                float2 f00 = *reinterpret_cast<const float2*>(p0 + k0);
                float2 f10 = *reinterpret_cast<const float2*>(p1 + k0);
                float2 f01 = *reinterpret_cast<const float2*>(p0 + k0 + 8);
                float2 f11 = *reinterpret_cast<const float2*>(p1 + k0 + 8);
                unsigned a[4], al[4];
                cvt_split(f00, a[0], al[0]);
                cvt_split(f10, a[1], al[1]);
                cvt_split(f01, a[2], al[2]);
                cvt_split(f11, a[3], al[3]);
                int off = k0 * 2;
                unsigned b[2], bl[2];
                b[0]  = *reinterpret_cast<const unsigned*>(bh + off);
                b[1]  = *reinterpret_cast<const unsigned*>(bh + off + 16);
                bl[0] = *reinterpret_cast<const unsigned*>(blp + off);
                bl[1] = *reinterpret_cast<const unsigned*>(blp + off + 16);
                mma16816(acc, a, b);
                mma16816(acc, a, bl);
                mma16816(acc, al, b);
            }
            // fp32 tail: k = 64,65
            float p64_0 = p0[64], p65_0 = p0[65];
            float p64_1 = p1[64], p65_1 = p1[65];
            #pragma unroll
            for (int e = 0; e < 2; ++e) {
                int dd = n0 + kq + e;
                float vt64 = vtail[dd], vt65 = vtail[32 + dd];
                float c0 = acc[e]     + p64_0 * vt64 + p65_0 * vt65;
                float c1 = acc[2 + e] + p64_1 * vt64 + p65_1 * vt65;
                if (r0 < 66) oo[r0 * OO_STRIDE + dd] = c0;
                if (r1 < 66) oo[r1 * OO_STRIDE + dd] = c1;
            }
        }
        __syncthreads();

        // ================= classifier + output (Wc from global, L2-hot) =================
        const size_t obase = (size_t)bt * (Jn * 256) + (size_t)h * 32;
        for (int t = tid; t < Jn * 32; t += 512) {
            int j = t >> 5, dd = t & 31;
            const float2* wr = reinterpret_cast<const float2*>(Wc + j * 66);
            float a = __ldg(bc + j);
            #pragma unroll 3
            for (int cc = 0; cc < 33; ++cc) {
                float2 w = __ldg(wr + cc);
                a += w.x * oo[(2 * cc) * OO_STRIDE + dd]
                   + w.y * oo[(2 * cc + 1) * OO_STRIDE + dd];
            }
            out[obase + (size_t)j * 256 + dd] = a;
        }
        __syncthreads();
    }
}

extern "C" void kernel_launch(void* const* d_in, const int* in_sizes, int n_in,
                              void* d_out, int out_size) {
    const float* x  = (const float*)d_in[0];
    const float* Wq = (const float*)d_in[1];
    const float* bq = (const float*)d_in[2];
    const float* Wk = (const float*)d_in[3];
    const float* bk = (const float*)d_in[4];
    const float* Wv = (const float*)d_in[5];
    const float* bv = (const float*)d_in[6];
    const float* Wc = (const float*)d_in[7];
    const float* bc = (const float*)d_in[8];
    float* out = (float*)d_out;

    repack_weights<<<(8 * 96 * 256 + 255) / 256, 256>>>(Wq, Wk, Wv);

    int blocks = in_sizes[0] / (Sn * 256);   // B*T = 3072
    cudaFuncSetAttribute(mha_fused_kernel,
                         cudaFuncAttributeMaxDynamicSharedMemorySize, SMEM_BYTES);
    mha_fused_kernel<<<blocks, 512, SMEM_BYTES>>>(x, bq, bk, bv, Wc, bc, out);
}

// round 11
// speedup vs baseline: 1.1615x; 1.1615x over previous
#include <cuda_runtime.h>
#include <cuda_fp16.h>
#include <cstdint>
#include <math.h>
#include <float.h>

constexpr int Hh = 8;
constexpr int Jn = 22;
constexpr int Sn = 66;
#define NEGV (-9e15f)

// ---------------- smem byte layout ----------------
constexpr int XH_OFF    = 0;        // x hi: 66 x 264 halfs
constexpr int XL_OFF    = 34848;    // x lo
constexpr int WH_OFF    = 69696;    // W hi: 96 x 264 halfs (dead after proj)
constexpr int WL_OFF    = 120384;   // W lo
// aliases inside W region (live softmax..PV; W(h+1) prefetch is issued after PV)
constexpr int PH_OFF    = 69696;    // P hi: 66 x 72 halfs (144B rows)
constexpr int PL_OFF    = 79200;    // P lo
constexpr int PTAIL_OFF = 88704;    // P cols 64,65 fp32: 66 x 2
constexpr int QS_OFFB   = 171072;   // qs fp32 66x33 (dead after scores)
constexpr int KT_OFFB   = 179792;   // kt fp32 32x68 (16B ALIGNED; dead after scores)
constexpr int OO_OFFB   = 171072;   // oo fp32 68x33 aliases qs/kt (live PV..cls)
constexpr int VTH_OFF   = 188496;   // v^T hi: 32 x 72 halfs
constexpr int VTL_OFF   = 193104;   // v^T lo
constexpr int VTAIL_OFF = 197712;   // V rows 64,65 fp32: 2 x 32
constexpr int PP_OFFB   = 197968;   // pp fp32 66 x 67
constexpr int WC_OFFB   = 215664;   // wc fp32 22 x 68 (16B aligned)
constexpr int BIAS_OFFB = 221648;   // 96 floats
constexpr int SMEM_BYTES = 222032;

constexpr int QS_STRIDE = 33, KT_STRIDE = 68, PP_STRIDE = 67, OO_STRIDE = 33, WC_STRIDE = 68;

typedef unsigned long long ull;

// pre-split weights in global, [h][n][k] layout, scaled x16
__device__ __align__(16) __half g_Wh[8 * 96 * 256];
__device__ __align__(16) __half g_Wl[8 * 96 * 256];

__global__ void repack_weights(const float* __restrict__ Wq,
                               const float* __restrict__ Wk,
                               const float* __restrict__ Wv) {
    int i = blockIdx.x * blockDim.x + threadIdx.x;
    if (i >= 8 * 96 * 256) return;
    int k = i & 255;
    int n = (i >> 8) % 96;
    int h = i / (96 * 256);
    const float* Wsrc = (n < 32) ? Wq : (n < 64 ? Wk : Wv);
    float w = 16.0f * Wsrc[(h * 32 + (n & 31)) * 256 + k];
    __half hi = __float2half_rn(w);
    __half lo = __float2half_rn(w - __half2float(hi));
    g_Wh[i] = hi;
    g_Wl[i] = lo;
}

// ---------------- device helpers ----------------
static __device__ __forceinline__ ull pk2(float a, float b) {
    ull r; asm("mov.b64 %0, {%1,%2};" : "=l"(r) : "f"(a), "f"(b)); return r;
}
static __device__ __forceinline__ void upk2(ull v, float &a, float &b) {
    asm("mov.b64 {%0,%1}, %2;" : "=f"(a), "=f"(b) : "l"(v));
}
static __device__ __forceinline__ ull ffma2(ull a, ull b, ull c) {
    ull d; asm("fma.rn.f32x2 %0, %1, %2, %3;" : "=l"(d) : "l"(a), "l"(b), "l"(c)); return d;
}
static __device__ __forceinline__ void cp16(unsigned dst, const void* src) {
    asm volatile("cp.async.ca.shared.global [%0], [%1], 16;" :: "r"(dst), "l"(src));
}
static __device__ __forceinline__ void cp_commit() { asm volatile("cp.async.commit_group;"); }
static __device__ __forceinline__ void cp_wait0()  { asm volatile("cp.async.wait_group 0;"); }

static __device__ __forceinline__ void mma16816(float* c, const unsigned* a, const unsigned* b) {
    asm volatile("mma.sync.aligned.m16n8k16.row.col.f32.f16.f16.f32 "
        "{%0,%1,%2,%3}, {%4,%5,%6,%7}, {%8,%9}, {%0,%1,%2,%3};"
        : "+f"(c[0]), "+f"(c[1]), "+f"(c[2]), "+f"(c[3])
        : "r"(a[0]), "r"(a[1]), "r"(a[2]), "r"(a[3]), "r"(b[0]), "r"(b[1]));
}

__global__ __launch_bounds__(512, 1)
void mha_fused_kernel(const float* __restrict__ x,
                      const float* __restrict__ bq,
                      const float* __restrict__ bk,
                      const float* __restrict__ bv,
                      const float* __restrict__ Wc, const float* __restrict__ bc,
                      float* __restrict__ out)
{
    extern __shared__ float sm[];
    char* smc = reinterpret_cast<char*>(sm);
    float* qs      = reinterpret_cast<float*>(smc + QS_OFFB);
    float* kt      = reinterpret_cast<float*>(smc + KT_OFFB);
    float* oo      = reinterpret_cast<float*>(smc + OO_OFFB);
    float* pp      = reinterpret_cast<float*>(smc + PP_OFFB);
    float* ptail   = reinterpret_cast<float*>(smc + PTAIL_OFF);
    float* vtail   = reinterpret_cast<float*>(smc + VTAIL_OFF);
    float* wcs     = reinterpret_cast<float*>(smc + WC_OFFB);
    float* biasArr = reinterpret_cast<float*>(smc + BIAS_OFFB);

    const int bt   = blockIdx.x;
    const int tid  = threadIdx.x;
    const int lane = tid & 31;
    const int wid  = tid >> 5;
    const int tm   = lane;

    const unsigned sbase = (unsigned)__cvta_generic_to_shared(smc);

    // ---- prologue: stage W(0) via cp.async ----
    {
        const char* srcH = reinterpret_cast<const char*>(g_Wh);
        const char* srcL = reinterpret_cast<const char*>(g_Wl);
        for (int c = tid; c < 6144; c += 512) {
            int half_sel = c >= 3072;
            int cc = c - (half_sel ? 3072 : 0);
            int n = cc >> 5, ch = cc & 31;
            const char* s = (half_sel ? srcL : srcH) + n * 512 + ch * 16;
            unsigned d = sbase + (half_sel ? WL_OFF : WH_OFF) + n * 528 + ch * 16;
            cp16(d, s);
        }
        cp_commit();
    }
    // ---- x fp32 -> fp16 hi/lo split ----
    {
        const float* xg = x + (size_t)bt * (Sn * 256);
        for (int t = tid; t < Sn * 256; t += 512) {
            int r = t >> 8, k = t & 255;
            float xv = xg[t];
            __half hi = __float2half_rn(xv);
            __half lo = __float2half_rn(xv - __half2float(hi));
            *reinterpret_cast<__half*>(smc + XH_OFF + r * 528 + k * 2) = hi;
            *reinterpret_cast<__half*>(smc + XL_OFF + r * 528 + k * 2) = lo;
        }
    }
    // ---- wc (+pad cols) ----
    for (int idx = tid; idx < 22 * 68; idx += 512) {
        int j = idx / 68, c = idx - j * 68;
        wcs[idx] = (c < 66) ? Wc[j * 66 + c] : 0.0f;
    }

    const float scale = 0.17677669529663687f; // 1/sqrt(32)

    for (int h = 0; h < Hh; ++h) {
        cp_wait0();
        if (tid < 96) {
            const float* bsrc = (tid < 32) ? bq : (tid < 64 ? bk : bv);
            biasArr[tid] = bsrc[h * 32 + (tid & 31)];
        }
        __syncthreads();   // W(h), bias visible

        // ================= QKV projection (HMMA, fp16 2-term split) =================
        for (int t = wid; t < 20; t += 16) {
            int mt = t >> 2, nt = t & 3;
            int m0 = mt * 16, n0 = nt * 24;
            int g = lane >> 2, kq = (lane & 3) * 2;
            int r0 = m0 + g, r1 = r0 + 8;
            int r0c = (r0 < 66) ? r0 : 65;
            int r1c = (r1 < 66) ? r1 : 65;
            const char* xh0 = smc + XH_OFF + r0c * 528;
            const char* xh1 = smc + XH_OFF + r1c * 528;
            const char* xl0 = smc + XL_OFF + r0c * 528;
            const char* xl1 = smc + XL_OFF + r1c * 528;
            const char* wh0 = smc + WH_OFF + (n0 + g) * 528;
            const char* wh1 = wh0 + 8 * 528;
            const char* wh2 = wh0 + 16 * 528;
            const char* wl0 = smc + WL_OFF + (n0 + g) * 528;
            const char* wl1 = wl0 + 8 * 528;
            const char* wl2 = wl0 + 16 * 528;

            float acc[3][4];
            #pragma unroll
            for (int j = 0; j < 3; ++j)
                #pragma unroll
                for (int e = 0; e < 4; ++e) acc[j][e] = 0.0f;

            #pragma unroll
            for (int ks = 0; ks < 16; ++ks) {
                int off = (ks * 16 + kq) * 2;
                unsigned a[4], al[4];
                a[0]  = *reinterpret_cast<const unsigned*>(xh0 + off);
                a[1]  = *reinterpret_cast<const unsigned*>(xh1 + off);
                a[2]  = *reinterpret_cast<const unsigned*>(xh0 + off + 16);
                a[3]  = *reinterpret_cast<const unsigned*>(xh1 + off + 16);
                al[0] = *reinterpret_cast<const unsigned*>(xl0 + off);
                al[1] = *reinterpret_cast<const unsigned*>(xl1 + off);
                al[2] = *reinterpret_cast<const unsigned*>(xl0 + off + 16);
                al[3] = *reinterpret_cast<const unsigned*>(xl1 + off + 16);

                unsigned b[2], bl[2];
                b[0]  = *reinterpret_cast<const unsigned*>(wh0 + off);
                b[1]  = *reinterpret_cast<const unsigned*>(wh0 + off + 16);
                bl[0] = *reinterpret_cast<const unsigned*>(wl0 + off);
                bl[1] = *reinterpret_cast<const unsigned*>(wl0 + off + 16);
                mma16816(acc[0], a, b);
                mma16816(acc[0], a, bl);
                mma16816(acc[0], al, b);

                b[0]  = *reinterpret_cast<const unsigned*>(wh1 + off);
                b[1]  = *reinterpret_cast<const unsigned*>(wh1 + off + 16);
                bl[0] = *reinterpret_cast<const unsigned*>(wl1 + off);
                bl[1] = *reinterpret_cast<const unsigned*>(wl1 + off + 16);
                mma16816(acc[1], a, b);
                mma16816(acc[1], a, bl);
                mma16816(acc[1], al, b);

                b[0]  = *reinterpret_cast<const unsigned*>(wh2 + off);
                b[1]  = *reinterpret_cast<const unsigned*>(wh2 + off + 16);
                bl[0] = *reinterpret_cast<const unsigned*>(wl2 + off);
                bl[1] = *reinterpret_cast<const unsigned*>(wl2 + off + 16);
                mma16816(acc[2], a, b);
                mma16816(acc[2], a, bl);
                mma16816(acc[2], al, b);
            }

            // epilogue: x1/16, +bias; q,k fp32; v fp16 hi/lo (+fp32 tail rows)
            #pragma unroll
            for (int j = 0; j < 3; ++j) {
                int cb = n0 + 8 * j + kq;
                #pragma unroll
                for (int e = 0; e < 2; ++e) {
                    int col = cb + e;
                    float bb = biasArr[col];
                    float v0 = acc[j][e]     * 0.0625f + bb;
                    float v1 = acc[j][2 + e] * 0.0625f + bb;
                    if (col < 32) {
                        if (r0 < 66) qs[r0 * QS_STRIDE + col] = v0;
                        if (r1 < 66) qs[r1 * QS_STRIDE + col] = v1;
                    } else if (col < 64) {
                        if (r0 < 66) kt[(col - 32) * KT_STRIDE + r0] = v0;
                        if (r1 < 66) kt[(col - 32) * KT_STRIDE + r1] = v1;
                    } else {
                        int dd = col - 64;
                        v0 = fmaxf(v0, 0.0f);
                        v1 = fmaxf(v1, 0.0f);
                        if (r0 < 66) {
                            __half h0 = __float2half_rn(v0);
                            __half l0 = __float2half_rn(v0 - __half2float(h0));
                            *reinterpret_cast<__half*>(smc + VTH_OFF + dd * 144 + r0 * 2) = h0;
                            *reinterpret_cast<__half*>(smc + VTL_OFF + dd * 144 + r0 * 2) = l0;
                            if (r0 >= 64) vtail[(r0 - 64) * 32 + dd] = v0;
                        }
                        if (r1 < 66) {
                            __half h1 = __float2half_rn(v1);
                            __half l1 = __float2half_rn(v1 - __half2float(h1));
                            *reinterpret_cast<__half*>(smc + VTH_OFF + dd * 144 + r1 * 2) = h1;
                            *reinterpret_cast<__half*>(smc + VTL_OFF + dd * 144 + r1 * 2) = l1;
                            if (r1 >= 64) vtail[(r1 - 64) * 32 + dd] = v1;
                        }
                    }
                }
            }
        }
        __syncthreads();

        // ================= scores (fp32 FFMA2, R8-proven) =================
        {
            int j0 = wid * 4;
            ull acc[2][2] = {{0ULL, 0ULL}, {0ULL, 0ULL}};
            const float* q0 = qs + tm * QS_STRIDE;
            const float* q1 = qs + (tm + 32) * QS_STRIDE;
            #pragma unroll 8
            for (int d = 0; d < 32; ++d) {
                longlong2 B = *reinterpret_cast<const longlong2*>(kt + d * KT_STRIDE + j0);
                float a0 = q0[d], a1 = q1[d];
                ull u0 = pk2(a0, a0), u1 = pk2(a1, a1);
                acc[0][0] = ffma2(u0, (ull)B.x, acc[0][0]);
                acc[0][1] = ffma2(u0, (ull)B.y, acc[0][1]);
                acc[1][0] = ffma2(u1, (ull)B.x, acc[1][0]);
                acc[1][1] = ffma2(u1, (ull)B.y, acc[1][1]);
            }
            #pragma unroll
            for (int u = 0; u < 2; ++u) {
                int i = tm + 32 * u;
                #pragma unroll
                for (int jp = 0; jp < 2; ++jp) {
                    float s0, s1;
                    upk2(acc[u][jp], s0, s1);
                    int j = j0 + 2 * jp;
                    bool m0 = (i < Jn && j     >= 2 * Jn) || (i >= 2 * Jn && j     < Jn);
                    bool m1 = (i < Jn && j + 1 >= 2 * Jn) || (i >= 2 * Jn && j + 1 < Jn);
                    pp[i * PP_STRIDE + j]     = m0 ? 0.0f : s0 * scale;
                    pp[i * PP_STRIDE + j + 1] = m1 ? 0.0f : s1 * scale;
                }
            }
        }
        if (tid < 260) {   // rows 64,65 all j; cols 64,65 for i<64
            int i, j;
            if (tid < 132) { i = 64 + tid / 66; j = tid % 66; }
            else { int t2 = tid - 132; i = t2 >> 1; j = 64 + (t2 & 1); }
            bool masked = (i < Jn && j >= 2 * Jn) || (i >= 2 * Jn && j < Jn);
            float s = 0.0f;
            if (!masked) {
                const float* qi = qs + i * QS_STRIDE;
                float d0 = 0.0f;
                #pragma unroll 8
                for (int d = 0; d < 32; ++d) d0 += qi[d] * kt[d * KT_STRIDE + j];
                s = d0 * scale;
            }
            pp[i * PP_STRIDE + j] = s;
        }
        __syncthreads();

        // ========== softmax (half-warp per row) + fused fp16 split of P ==========
        {
            const int l16 = lane & 15;
            for (int r = (wid << 1) + (lane >> 4); r < Sn; r += 32) {
                float* row = pp + r * PP_STRIDE;
                float v0 = row[l16];
                float v1 = row[l16 + 16];
                float v2 = row[l16 + 32];
                float v3 = row[l16 + 48];
                float v4 = (l16 < 2) ? row[64 + l16] : -FLT_MAX;
                float m = fmaxf(fmaxf(fmaxf(v0, v1), fmaxf(v2, v3)), v4);
                #pragma unroll
                for (int o = 8; o; o >>= 1) m = fmaxf(m, __shfl_xor_sync(0xffffffffu, m, o, 16));
                float thr = m * (1.0f / 9.0f);
                float t0 = (fabsf(v0) <= thr) ? NEGV : v0;
                float t1 = (fabsf(v1) <= thr) ? NEGV : v1;
                float t2 = (fabsf(v2) <= thr) ? NEGV : v2;
                float t3 = (fabsf(v3) <= thr) ? NEGV : v3;
                float t4 = (l16 < 2) ? ((fabsf(v4) <= thr) ? NEGV : v4) : -FLT_MAX;
                float M2 = fmaxf(fmaxf(fmaxf(t0, t1), fmaxf(t2, t3)), t4);
                #pragma unroll
                for (int o = 8; o; o >>= 1) M2 = fmaxf(M2, __shfl_xor_sync(0xffffffffu, M2, o, 16));
                float e0 = __expf(t0 - M2);
                float e1 = __expf(t1 - M2);
                float e2 = __expf(t2 - M2);
                float e3 = __expf(t3 - M2);
                float e4 = (l16 < 2) ? __expf(t4 - M2) : 0.0f;
                float s = e0 + e1 + e2 + e3 + e4;
                #pragma unroll
                for (int o = 8; o; o >>= 1) s += __shfl_xor_sync(0xffffffffu, s, o, 16);
                float inv = 1.0f / s;
                char* phr = smc + PH_OFF + r * 144;
                char* plr = smc + PL_OFF + r * 144;
                #pragma unroll
                for (int q = 0; q < 4; ++q) {
                    float p = (q == 0 ? e0 : q == 1 ? e1 : q == 2 ? e2 : e3) * inv;
                    int c = l16 + 16 * q;
                    __half hp = __float2half_rn(p);
                    __half lp = __float2half_rn(p - __half2float(hp));
                    *reinterpret_cast<__half*>(phr + c * 2) = hp;
                    *reinterpret_cast<__half*>(plr + c * 2) = lp;
                }
                if (l16 < 2) {
                    float p = e4 * inv;
                    int c = 64 + l16;
                    __half hp = __float2half_rn(p);
                    __half lp = __float2half_rn(p - __half2float(hp));
                    *reinterpret_cast<__half*>(phr + c * 2) = hp;
                    *reinterpret_cast<__half*>(plr + c * 2) = lp;
                    ptail[r * 2 + l16] = p;
                }
            }
        }
        __syncthreads();

        // ================= P @ V via HMMA (P pre-split) =================
        for (int t = wid; t < 20; t += 16) {
            int mt = t >> 2, nt = t & 3;
            int m0 = mt * 16, n0 = nt * 8;
            int g = lane >> 2, kq = (lane & 3) * 2;
            int r0 = m0 + g, r1 = r0 + 8;
            int r0c = (r0 < 66) ? r0 : 65;
            int r1c = (r1 < 66) ? r1 : 65;
            const char* ah0 = smc + PH_OFF + r0c * 144;
            const char* ah1 = smc + PH_OFF + r1c * 144;
            const char* al0 = smc + PL_OFF + r0c * 144;
            const char* al1 = smc + PL_OFF + r1c * 144;
            const char* bh  = smc + VTH_OFF + (n0 + g) * 144;
            const char* blp = smc + VTL_OFF + (n0 + g) * 144;

            float acc[4] = {0.0f, 0.0f, 0.0f, 0.0f};
            #pragma unroll
            for (int ks = 0; ks < 4; ++ks) {
                int off = (ks * 16 + kq) * 2;
                unsigned a[4], al[4], b[2], bl[2];
                a[0]  = *reinterpret_cast<const unsigned*>(ah0 + off);
                a[1]  = *reinterpret_cast<const unsigned*>(ah1 + off);
                a[2]  = *reinterpret_cast<const unsigned*>(ah0 + off + 16);
                a[3]  = *reinterpret_cast<const unsigned*>(ah1 + off + 16);
                al[0] = *reinterpret_cast<const unsigned*>(al0 + off);
                al[1] = *reinterpret_cast<const unsigned*>(al1 + off);
                al[2] = *reinterpret_cast<const unsigned*>(al0 + off + 16);
                al[3] = *reinterpret_cast<const unsigned*>(al1 + off + 16);
                b[0]  = *reinterpret_cast<const unsigned*>(bh + off);
                b[1]  = *reinterpret_cast<const unsigned*>(bh + off + 16);
                bl[0] = *reinterpret_cast<const unsigned*>(blp + off);
                bl[1] = *reinterpret_cast<const unsigned*>(blp + off + 16);
                mma16816(acc, a, b);
                mma16816(acc, a, bl);
                mma16816(acc, al, b);
            }
            // fp32 tail k = 64,65
            float p64_0 = ptail[r0c * 2], p65_0 = ptail[r0c * 2 + 1];
            float p64_1 = ptail[r1c * 2], p65_1 = ptail[r1c * 2 + 1];
            #pragma unroll
            for (int e = 0; e < 2; ++e) {
                int dd = n0 + kq + e;
                float vt64 = vtail[dd], vt65 = vtail[32 + dd];
                float c0 = acc[e]     + p64_0 * vt64 + p65_0 * vt65;
                float c1 = acc[2 + e] + p64_1 * vt64 + p65_1 * vt65;
                if (r0 < 66) oo[r0 * OO_STRIDE + dd] = c0;
                if (r1 < 66) oo[r1 * OO_STRIDE + dd] = c1;
            }
        }
        // oo pad rows 66,67 (aliased region rewritten each head)
        if (tid < 66) oo[66 * OO_STRIDE + tid] = 0.0f;
        __syncthreads();

        // ---- prefetch W(h+1) (writes alias P region; safe after PV sync) ----
        if (h + 1 < Hh) {
            const char* srcH = reinterpret_cast<const char*>(g_Wh) + (size_t)(h + 1) * 49152;
            const char* srcL = reinterpret_cast<const char*>(g_Wl) + (size_t)(h + 1) * 49152;
            for (int c = tid; c < 6144; c += 512) {
                int half_sel = c >= 3072;
                int cc = c - (half_sel ? 3072 : 0);
                int n = cc >> 5, ch = cc & 31;
                const char* s = (half_sel ? srcL : srcH) + n * 512 + ch * 16;
                unsigned d = sbase + (half_sel ? WL_OFF : WH_OFF) + n * 528 + ch * 16;
                cp16(d, s);
            }
            cp_commit();
        }

        // ================= classifier + output =================
        const size_t obase = (size_t)bt * (Jn * 256) + (size_t)h * 32;
        for (int t = tid; t < Jn * 32; t += 512) {
            int j = t >> 5, dd = t & 31;
            const float4* wr = reinterpret_cast<const float4*>(wcs + j * WC_STRIDE);
            float a = __ldg(bc + j);
            #pragma unroll
            for (int cc = 0; cc < 17; ++cc) {
                float4 w = wr[cc];
                const float* ob = oo + (4 * cc) * OO_STRIDE + dd;
                a += w.x * ob[0] + w.y * ob[OO_STRIDE]
                   + w.z * ob[2 * OO_STRIDE] + w.w * ob[3 * OO_STRIDE];
            }
            out[obase + (size_t)j * 256 + dd] = a;
        }
        __syncthreads();
    }
}

extern "C" void kernel_launch(void* const* d_in, const int* in_sizes, int n_in,
                              void* d_out, int out_size) {
    const float* x  = (const float*)d_in[0];
    const float* Wq = (const float*)d_in[1];
    const float* bq = (const float*)d_in[2];
    const float* Wk = (const float*)d_in[3];
    const float* bk = (const float*)d_in[4];
    const float* Wv = (const float*)d_in[5];
    const float* bv = (const float*)d_in[6];
    const float* Wc = (const float*)d_in[7];
    const float* bc = (const float*)d_in[8];
    float* out = (float*)d_out;

    repack_weights<<<(8 * 96 * 256 + 255) / 256, 256>>>(Wq, Wk, Wv);

    int blocks = in_sizes[0] / (Sn * 256);   // B*T = 3072
    cudaFuncSetAttribute(mha_fused_kernel,
                         cudaFuncAttributeMaxDynamicSharedMemorySize, SMEM_BYTES);
    mha_fused_kernel<<<blocks, 512, SMEM_BYTES>>>(x, bq, bk, bv, Wc, bc, out);
}

// round 12
// speedup vs baseline: 1.2220x; 1.0521x over previous
#include <cuda_runtime.h>
#include <cuda_fp16.h>
#include <cstdint>
#include <math.h>
#include <float.h>

constexpr int Hh = 8;
constexpr int Jn = 22;
constexpr int Sn = 66;
constexpr int NT = 640;   // 20 warps
#define NEGV (-9e15f)

// ---------------- smem byte layout ----------------
constexpr int XH_OFF    = 0;        // x hi: 66 x 264 halfs
constexpr int XL_OFF    = 34848;    // x lo
constexpr int WH_OFF    = 69696;    // W hi: 96 x 264 halfs (dead after proj)
constexpr int WL_OFF    = 120384;   // W lo
// aliases inside W region (live softmax..PV; W(h+1) prefetch is issued after PV)
constexpr int PH_OFF    = 69696;    // P hi: 66 x 72 halfs (144B rows)
constexpr int PL_OFF    = 79200;    // P lo
constexpr int PTAIL_OFF = 88704;    // P cols 64,65 fp32: 66 x 2
constexpr int QS_OFFB   = 171072;   // qs fp32 66x33 (dead after scores)
constexpr int KT_OFFB   = 179792;   // kt fp32 32x68 (16B aligned; dead after scores)
constexpr int OO_OFFB   = 171072;   // oo fp32 68x33 aliases qs/kt (live PV..cls)
constexpr int VTH_OFF   = 188496;   // v^T hi: 32 x 72 halfs
constexpr int VTL_OFF   = 193104;   // v^T lo
constexpr int VTAIL_OFF = 197712;   // V rows 64,65 fp32: 2 x 32
constexpr int PP_OFFB   = 197968;   // pp fp32 66 x 67
constexpr int WC_OFFB   = 215664;   // wc fp32 22 x 68 (16B aligned)
constexpr int BIAS_OFFB = 221648;   // 96 floats
constexpr int SMEM_BYTES = 222032;

constexpr int QS_STRIDE = 33, KT_STRIDE = 68, PP_STRIDE = 67, OO_STRIDE = 33, WC_STRIDE = 68;

typedef unsigned long long ull;

// pre-split weights in global, [h][n][k] layout, scaled x16
__device__ __align__(16) __half g_Wh[8 * 96 * 256];
__device__ __align__(16) __half g_Wl[8 * 96 * 256];

__global__ void repack_weights(const float* __restrict__ Wq,
                               const float* __restrict__ Wk,
                               const float* __restrict__ Wv) {
    int i = blockIdx.x * blockDim.x + threadIdx.x;
    if (i >= 8 * 96 * 256) return;
    int k = i & 255;
    int n = (i >> 8) % 96;
    int h = i / (96 * 256);
    const float* Wsrc = (n < 32) ? Wq : (n < 64 ? Wk : Wv);
    float w = 16.0f * Wsrc[(h * 32 + (n & 31)) * 256 + k];
    __half hi = __float2half_rn(w);
    __half lo = __float2half_rn(w - __half2float(hi));
    g_Wh[i] = hi;
    g_Wl[i] = lo;
}

// ---------------- device helpers ----------------
static __device__ __forceinline__ ull pk2(float a, float b) {
    ull r; asm("mov.b64 %0, {%1,%2};" : "=l"(r) : "f"(a), "f"(b)); return r;
}
static __device__ __forceinline__ void upk2(ull v, float &a, float &b) {
    asm("mov.b64 {%0,%1}, %2;" : "=f"(a), "=f"(b) : "l"(v));
}
static __device__ __forceinline__ ull ffma2(ull a, ull b, ull c) {
    ull d; asm("fma.rn.f32x2 %0, %1, %2, %3;" : "=l"(d) : "l"(a), "l"(b), "l"(c)); return d;
}
static __device__ __forceinline__ void cp16(unsigned dst, const void* src) {
    asm volatile("cp.async.ca.shared.global [%0], [%1], 16;" :: "r"(dst), "l"(src));
}
static __device__ __forceinline__ void cp_commit() { asm volatile("cp.async.commit_group;"); }
static __device__ __forceinline__ void cp_wait0()  { asm volatile("cp.async.wait_group 0;"); }

static __device__ __forceinline__ void mma16816(float* c, const unsigned* a, const unsigned* b) {
    asm volatile("mma.sync.aligned.m16n8k16.row.col.f32.f16.f16.f32 "
        "{%0,%1,%2,%3}, {%4,%5,%6,%7}, {%8,%9}, {%0,%1,%2,%3};"
        : "+f"(c[0]), "+f"(c[1]), "+f"(c[2]), "+f"(c[3])
        : "r"(a[0]), "r"(a[1]), "r"(a[2]), "r"(a[3]), "r"(b[0]), "r"(b[1]));
}

__global__ __launch_bounds__(NT, 1)
void mha_fused_kernel(const float* __restrict__ x,
                      const float* __restrict__ bq,
                      const float* __restrict__ bk,
                      const float* __restrict__ bv,
                      const float* __restrict__ Wc, const float* __restrict__ bc,
                      float* __restrict__ out)
{
    extern __shared__ float sm[];
    char* smc = reinterpret_cast<char*>(sm);
    float* qs      = reinterpret_cast<float*>(smc + QS_OFFB);
    float* kt      = reinterpret_cast<float*>(smc + KT_OFFB);
    float* oo      = reinterpret_cast<float*>(smc + OO_OFFB);
    float* pp      = reinterpret_cast<float*>(smc + PP_OFFB);
    float* ptail   = reinterpret_cast<float*>(smc + PTAIL_OFF);
    float* vtail   = reinterpret_cast<float*>(smc + VTAIL_OFF);
    float* wcs     = reinterpret_cast<float*>(smc + WC_OFFB);
    float* biasArr = reinterpret_cast<float*>(smc + BIAS_OFFB);

    const int bt   = blockIdx.x;
    const int tid  = threadIdx.x;
    const int lane = tid & 31;
    const int wid  = tid >> 5;
    const int tm   = lane;

    const unsigned sbase = (unsigned)__cvta_generic_to_shared(smc);

    // ---- prologue: stage W(0) via cp.async ----
    {
        const char* srcH = reinterpret_cast<const char*>(g_Wh);
        const char* srcL = reinterpret_cast<const char*>(g_Wl);
        for (int c = tid; c < 6144; c += NT) {
            int half_sel = c >= 3072;
            int cc = c - (half_sel ? 3072 : 0);
            int n = cc >> 5, ch = cc & 31;
            const char* s = (half_sel ? srcL : srcH) + n * 512 + ch * 16;
            unsigned d = sbase + (half_sel ? WL_OFF : WH_OFF) + n * 528 + ch * 16;
            cp16(d, s);
        }
        cp_commit();
    }
    // ---- x fp32 -> fp16 hi/lo split ----
    {
        const float* xg = x + (size_t)bt * (Sn * 256);
        for (int t = tid; t < Sn * 256; t += NT) {
            int r = t >> 8, k = t & 255;
            float xv = xg[t];
            __half hi = __float2half_rn(xv);
            __half lo = __float2half_rn(xv - __half2float(hi));
            *reinterpret_cast<__half*>(smc + XH_OFF + r * 528 + k * 2) = hi;
            *reinterpret_cast<__half*>(smc + XL_OFF + r * 528 + k * 2) = lo;
        }
    }
    // ---- wc (+pad cols) ----
    for (int idx = tid; idx < 22 * 68; idx += NT) {
        int j = idx / 68, c = idx - j * 68;
        wcs[idx] = (c < 66) ? Wc[j * 66 + c] : 0.0f;
    }

    const float scale = 0.17677669529663687f; // 1/sqrt(32)

    for (int h = 0; h < Hh; ++h) {
        cp_wait0();
        if (tid < 96) {
            const float* bsrc = (tid < 32) ? bq : (tid < 64 ? bk : bv);
            biasArr[tid] = bsrc[h * 32 + (tid & 31)];
        }
        __syncthreads();   // W(h), bias visible

        // ================= QKV projection (HMMA): one job per warp =================
        if (wid < 20) {
            int t = wid;
            int mt = t >> 2, nt = t & 3;
            int m0 = mt * 16, n0 = nt * 24;
            int g = lane >> 2, kq = (lane & 3) * 2;
            int r0 = m0 + g, r1 = r0 + 8;
            int r0c = (r0 < 66) ? r0 : 65;
            int r1c = (r1 < 66) ? r1 : 65;
            const char* xh0 = smc + XH_OFF + r0c * 528;
            const char* xh1 = smc + XH_OFF + r1c * 528;
            const char* xl0 = smc + XL_OFF + r0c * 528;
            const char* xl1 = smc + XL_OFF + r1c * 528;
            const char* wh0 = smc + WH_OFF + (n0 + g) * 528;
            const char* wh1 = wh0 + 8 * 528;
            const char* wh2 = wh0 + 16 * 528;
            const char* wl0 = smc + WL_OFF + (n0 + g) * 528;
            const char* wl1 = wl0 + 8 * 528;
            const char* wl2 = wl0 + 16 * 528;

            float acc[3][4];
            #pragma unroll
            for (int j = 0; j < 3; ++j)
                #pragma unroll
                for (int e = 0; e < 4; ++e) acc[j][e] = 0.0f;

            #pragma unroll
            for (int ks = 0; ks < 16; ++ks) {
                int off = (ks * 16 + kq) * 2;
                unsigned a[4], al[4];
                a[0]  = *reinterpret_cast<const unsigned*>(xh0 + off);
                a[1]  = *reinterpret_cast<const unsigned*>(xh1 + off);
                a[2]  = *reinterpret_cast<const unsigned*>(xh0 + off + 16);
                a[3]  = *reinterpret_cast<const unsigned*>(xh1 + off + 16);
                al[0] = *reinterpret_cast<const unsigned*>(xl0 + off);
                al[1] = *reinterpret_cast<const unsigned*>(xl1 + off);
                al[2] = *reinterpret_cast<const unsigned*>(xl0 + off + 16);
                al[3] = *reinterpret_cast<const unsigned*>(xl1 + off + 16);

                unsigned b[2], bl[2];
                b[0]  = *reinterpret_cast<const unsigned*>(wh0 + off);
                b[1]  = *reinterpret_cast<const unsigned*>(wh0 + off + 16);
                bl[0] = *reinterpret_cast<const unsigned*>(wl0 + off);
                bl[1] = *reinterpret_cast<const unsigned*>(wl0 + off + 16);
                mma16816(acc[0], a, b);
                mma16816(acc[0], a, bl);
                mma16816(acc[0], al, b);

                b[0]  = *reinterpret_cast<const unsigned*>(wh1 + off);
                b[1]  = *reinterpret_cast<const unsigned*>(wh1 + off + 16);
                bl[0] = *reinterpret_cast<const unsigned*>(wl1 + off);
                bl[1] = *reinterpret_cast<const unsigned*>(wl1 + off + 16);
                mma16816(acc[1], a, b);
                mma16816(acc[1], a, bl);
                mma16816(acc[1], al, b);

                b[0]  = *reinterpret_cast<const unsigned*>(wh2 + off);
                b[1]  = *reinterpret_cast<const unsigned*>(wh2 + off + 16);
                bl[0] = *reinterpret_cast<const unsigned*>(wl2 + off);
                bl[1] = *reinterpret_cast<const unsigned*>(wl2 + off + 16);
                mma16816(acc[2], a, b);
                mma16816(acc[2], a, bl);
                mma16816(acc[2], al, b);
            }

            // epilogue: x1/16, +bias; q,k fp32; v fp16 hi/lo (+fp32 tail rows)
            #pragma unroll
            for (int j = 0; j < 3; ++j) {
                int cb = n0 + 8 * j + kq;
                #pragma unroll
                for (int e = 0; e < 2; ++e) {
                    int col = cb + e;
                    float bb = biasArr[col];
                    float v0 = acc[j][e]     * 0.0625f + bb;
                    float v1 = acc[j][2 + e] * 0.0625f + bb;
                    if (col < 32) {
                        if (r0 < 66) qs[r0 * QS_STRIDE + col] = v0;
                        if (r1 < 66) qs[r1 * QS_STRIDE + col] = v1;
                    } else if (col < 64) {
                        if (r0 < 66) kt[(col - 32) * KT_STRIDE + r0] = v0;
                        if (r1 < 66) kt[(col - 32) * KT_STRIDE + r1] = v1;
                    } else {
                        int dd = col - 64;
                        v0 = fmaxf(v0, 0.0f);
                        v1 = fmaxf(v1, 0.0f);
                        if (r0 < 66) {
                            __half h0 = __float2half_rn(v0);
                            __half l0 = __float2half_rn(v0 - __half2float(h0));
                            *reinterpret_cast<__half*>(smc + VTH_OFF + dd * 144 + r0 * 2) = h0;
                            *reinterpret_cast<__half*>(smc + VTL_OFF + dd * 144 + r0 * 2) = l0;
                            if (r0 >= 64) vtail[(r0 - 64) * 32 + dd] = v0;
                        }
                        if (r1 < 66) {
                            __half h1 = __float2half_rn(v1);
                            __half l1 = __float2half_rn(v1 - __half2float(h1));
                            *reinterpret_cast<__half*>(smc + VTH_OFF + dd * 144 + r1 * 2) = h1;
                            *reinterpret_cast<__half*>(smc + VTL_OFF + dd * 144 + r1 * 2) = l1;
                            if (r1 >= 64) vtail[(r1 - 64) * 32 + dd] = v1;
                        }
                    }
                }
            }
        }
        __syncthreads();

        // ================= scores: 16 warps GEMM + 4 warps cleanup (concurrent) =========
        if (wid < 16) {
            int j0 = wid * 4;
            ull acc[2][2] = {{0ULL, 0ULL}, {0ULL, 0ULL}};
            const float* q0 = qs + tm * QS_STRIDE;
            const float* q1 = qs + (tm + 32) * QS_STRIDE;
            #pragma unroll 8
            for (int d = 0; d < 32; ++d) {
                longlong2 B = *reinterpret_cast<const longlong2*>(kt + d * KT_STRIDE + j0);
                float a0 = q0[d], a1 = q1[d];
                ull u0 = pk2(a0, a0), u1 = pk2(a1, a1);
                acc[0][0] = ffma2(u0, (ull)B.x, acc[0][0]);
                acc[0][1] = ffma2(u0, (ull)B.y, acc[0][1]);
                acc[1][0] = ffma2(u1, (ull)B.x, acc[1][0]);
                acc[1][1] = ffma2(u1, (ull)B.y, acc[1][1]);
            }
            #pragma unroll
            for (int u = 0; u < 2; ++u) {
                int i = tm + 32 * u;
                #pragma unroll
                for (int jp = 0; jp < 2; ++jp) {
                    float s0, s1;
                    upk2(acc[u][jp], s0, s1);
                    int j = j0 + 2 * jp;
                    bool m0 = (i < Jn && j     >= 2 * Jn) || (i >= 2 * Jn && j     < Jn);
                    bool m1 = (i < Jn && j + 1 >= 2 * Jn) || (i >= 2 * Jn && j + 1 < Jn);
                    pp[i * PP_STRIDE + j]     = m0 ? 0.0f : s0 * scale;
                    pp[i * PP_STRIDE + j + 1] = m1 ? 0.0f : s1 * scale;
                }
            }
        } else {
            // cleanup: rows 64,65 (all j) + cols 64,65 (i<64) — 260 items on warps 16-19
            for (int idx = (wid - 16) * 32 + lane; idx < 260; idx += 128) {
                int i, j;
                if (idx < 132) { i = 64 + idx / 66; j = idx % 66; }
                else { int t2 = idx - 132; i = t2 >> 1; j = 64 + (t2 & 1); }
                bool masked = (i < Jn && j >= 2 * Jn) || (i >= 2 * Jn && j < Jn);
                float s = 0.0f;
                if (!masked) {
                    const float* qi = qs + i * QS_STRIDE;
                    float d0 = 0.0f;
                    #pragma unroll 8
                    for (int d = 0; d < 32; ++d) d0 += qi[d] * kt[d * KT_STRIDE + j];
                    s = d0 * scale;
                }
                pp[i * PP_STRIDE + j] = s;
            }
        }
        __syncthreads();

        // ========== softmax (half-warp per row, 40 half-warps) + fused fp16 split ==========
        {
            const int l16 = lane & 15;
            for (int r = (wid << 1) + (lane >> 4); r < Sn; r += 40) {
                float* row = pp + r * PP_STRIDE;
                float v0 = row[l16];
                float v1 = row[l16 + 16];
                float v2 = row[l16 + 32];
                float v3 = row[l16 + 48];
                float v4 = (l16 < 2) ? row[64 + l16] : -FLT_MAX;
                float m = fmaxf(fmaxf(fmaxf(v0, v1), fmaxf(v2, v3)), v4);
                #pragma unroll
                for (int o = 8; o; o >>= 1) m = fmaxf(m, __shfl_xor_sync(0xffffffffu, m, o, 16));
                float thr = m * (1.0f / 9.0f);
                float t0 = (fabsf(v0) <= thr) ? NEGV : v0;
                float t1 = (fabsf(v1) <= thr) ? NEGV : v1;
                float t2 = (fabsf(v2) <= thr) ? NEGV : v2;
                float t3 = (fabsf(v3) <= thr) ? NEGV : v3;
                float t4 = (l16 < 2) ? ((fabsf(v4) <= thr) ? NEGV : v4) : -FLT_MAX;
                float M2 = fmaxf(fmaxf(fmaxf(t0, t1), fmaxf(t2, t3)), t4);
                #pragma unroll
                for (int o = 8; o; o >>= 1) M2 = fmaxf(M2, __shfl_xor_sync(0xffffffffu, M2, o, 16));
                float e0 = __expf(t0 - M2);
                float e1 = __expf(t1 - M2);
                float e2 = __expf(t2 - M2);
                float e3 = __expf(t3 - M2);
                float e4 = (l16 < 2) ? __expf(t4 - M2) : 0.0f;
                float s = e0 + e1 + e2 + e3 + e4;
                #pragma unroll
                for (int o = 8; o; o >>= 1) s += __shfl_xor_sync(0xffffffffu, s, o, 16);
                float inv = 1.0f / s;
                char* phr = smc + PH_OFF + r * 144;
                char* plr = smc + PL_OFF + r * 144;
                #pragma unroll
                for (int q = 0; q < 4; ++q) {
                    float p = (q == 0 ? e0 : q == 1 ? e1 : q == 2 ? e2 : e3) * inv;
                    int c = l16 + 16 * q;
                    __half hp = __float2half_rn(p);
                    __half lp = __float2half_rn(p - __half2float(hp));
                    *reinterpret_cast<__half*>(phr + c * 2) = hp;
                    *reinterpret_cast<__half*>(plr + c * 2) = lp;
                }
                if (l16 < 2) {
                    float p = e4 * inv;
                    int c = 64 + l16;
                    __half hp = __float2half_rn(p);
                    __half lp = __float2half_rn(p - __half2float(hp));
                    *reinterpret_cast<__half*>(phr + c * 2) = hp;
                    *reinterpret_cast<__half*>(plr + c * 2) = lp;
                    ptail[r * 2 + l16] = p;
                }
            }
        }
        __syncthreads();

        // ================= P @ V via HMMA: one job per warp =================
        if (wid < 20) {
            int t = wid;
            int mt = t >> 2, nt = t & 3;
            int m0 = mt * 16, n0 = nt * 8;
            int g = lane >> 2, kq = (lane & 3) * 2;
            int r0 = m0 + g, r1 = r0 + 8;
            int r0c = (r0 < 66) ? r0 : 65;
            int r1c = (r1 < 66) ? r1 : 65;
            const char* ah0 = smc + PH_OFF + r0c * 144;
            const char* ah1 = smc + PH_OFF + r1c * 144;
            const char* al0 = smc + PL_OFF + r0c * 144;
            const char* al1 = smc + PL_OFF + r1c * 144;
            const char* bh  = smc + VTH_OFF + (n0 + g) * 144;
            const char* blp = smc + VTL_OFF + (n0 + g) * 144;

            float acc[4] = {0.0f, 0.0f, 0.0f, 0.0f};
            #pragma unroll
            for (int ks = 0; ks < 4; ++ks) {
                int off = (ks * 16 + kq) * 2;
                unsigned a[4], al[4], b[2], bl[2];
                a[0]  = *reinterpret_cast<const unsigned*>(ah0 + off);
                a[1]  = *reinterpret_cast<const unsigned*>(ah1 + off);
                a[2]  = *reinterpret_cast<const unsigned*>(ah0 + off + 16);
                a[3]  = *reinterpret_cast<const unsigned*>(ah1 + off + 16);
                al[0] = *reinterpret_cast<const unsigned*>(al0 + off);
                al[1] = *reinterpret_cast<const unsigned*>(al1 + off);
                al[2] = *reinterpret_cast<const unsigned*>(al0 + off + 16);
                al[3] = *reinterpret_cast<const unsigned*>(al1 + off + 16);
                b[0]  = *reinterpret_cast<const unsigned*>(bh + off);
                b[1]  = *reinterpret_cast<const unsigned*>(bh + off + 16);
                bl[0] = *reinterpret_cast<const unsigned*>(blp + off);
                bl[1] = *reinterpret_cast<const unsigned*>(blp + off + 16);
                mma16816(acc, a, b);
                mma16816(acc, a, bl);
                mma16816(acc, al, b);
            }
            // fp32 tail k = 64,65
            float p64_0 = ptail[r0c * 2], p65_0 = ptail[r0c * 2 + 1];
            float p64_1 = ptail[r1c * 2], p65_1 = ptail[r1c * 2 + 1];
            #pragma unroll
            for (int e = 0; e < 2; ++e) {
                int dd = n0 + kq + e;
                float vt64 = vtail[dd], vt65 = vtail[32 + dd];
                float c0 = acc[e]     + p64_0 * vt64 + p65_0 * vt65;
                float c1 = acc[2 + e] + p64_1 * vt64 + p65_1 * vt65;
                if (r0 < 66) oo[r0 * OO_STRIDE + dd] = c0;
                if (r1 < 66) oo[r1 * OO_STRIDE + dd] = c1;
            }
        }
        // oo pad rows 66,67 (aliased region rewritten each head)
        if (tid < 66) oo[66 * OO_STRIDE + tid] = 0.0f;
        __syncthreads();

        // ---- prefetch W(h+1) (writes alias P region; safe after PV sync) ----
        if (h + 1 < Hh) {
            const char* srcH = reinterpret_cast<const char*>(g_Wh) + (size_t)(h + 1) * 49152;
            const char* srcL = reinterpret_cast<const char*>(g_Wl) + (size_t)(h + 1) * 49152;
            for (int c = tid; c < 6144; c += NT) {
                int half_sel = c >= 3072;
                int cc = c - (half_sel ? 3072 : 0);
                int n = cc >> 5, ch = cc & 31;
                const char* s = (half_sel ? srcL : srcH) + n * 512 + ch * 16;
                unsigned d = sbase + (half_sel ? WL_OFF : WH_OFF) + n * 528 + ch * 16;
                cp16(d, s);
            }
            cp_commit();
        }

        // ================= classifier + output =================
        const size_t obase = (size_t)bt * (Jn * 256) + (size_t)h * 32;
        for (int t = tid; t < Jn * 32; t += NT) {
            int j = t >> 5, dd = t & 31;
            const float4* wr = reinterpret_cast<const float4*>(wcs + j * WC_STRIDE);
            float a = __ldg(bc + j);
            #pragma unroll
            for (int cc = 0; cc < 17; ++cc) {
                float4 w = wr[cc];
                const float* ob = oo + (4 * cc) * OO_STRIDE + dd;
                a += w.x * ob[0] + w.y * ob[OO_STRIDE]
                   + w.z * ob[2 * OO_STRIDE] + w.w * ob[3 * OO_STRIDE];
            }
            out[obase + (size_t)j * 256 + dd] = a;
        }
        __syncthreads();
    }
}

extern "C" void kernel_launch(void* const* d_in, const int* in_sizes, int n_in,
                              void* d_out, int out_size) {
    const float* x  = (const float*)d_in[0];
    const float* Wq = (const float*)d_in[1];
    const float* bq = (const float*)d_in[2];
    const float* Wk = (const float*)d_in[3];
    const float* bk = (const float*)d_in[4];
    const float* Wv = (const float*)d_in[5];
    const float* bv = (const float*)d_in[6];
    const float* Wc = (const float*)d_in[7];
    const float* bc = (const float*)d_in[8];
    float* out = (float*)d_out;

    repack_weights<<<(8 * 96 * 256 + 255) / 256, 256>>>(Wq, Wk, Wv);

    int blocks = in_sizes[0] / (Sn * 256);   // B*T = 3072
    cudaFuncSetAttribute(mha_fused_kernel,
                         cudaFuncAttributeMaxDynamicSharedMemorySize, SMEM_BYTES);
    mha_fused_kernel<<<blocks, NT, SMEM_BYTES>>>(x, bq, bk, bv, Wc, bc, out);
}

// round 13
// speedup vs baseline: 1.2489x; 1.0221x over previous
#include <cuda_runtime.h>
#include <cuda_fp16.h>
#include <cstdint>
#include <math.h>
#include <float.h>

constexpr int Hh = 8;
constexpr int Jn = 22;
constexpr int Sn = 66;
constexpr int NT = 640;   // 20 warps
#define NEGV (-9e15f)

// ---------------- smem byte layout (P no longer aliases W) ----------------
constexpr int XH_OFF    = 0;        // x hi: 66 x 264 halfs
constexpr int XL_OFF    = 34848;    // x lo
constexpr int WH_OFF    = 69696;    // W hi (dead right after proj -> early prefetch)
constexpr int WL_OFF    = 120384;   // W lo                    ends 171072
// scratch region A: qs/kt (proj..scores) overlaid by P hi/lo+ptail (softmax..PV)
constexpr int QS_OFFB   = 171072;   // qs fp32 66x33 (8712B)
constexpr int KT_OFFB   = 179792;   // kt fp32 32x68 (16B aligned, 8704B) ends 188496
constexpr int PH_OFF    = 171072;   // P hi: 66 x 72 halfs (144B rows, 9504B)
constexpr int PL_OFF    = 180576;   // P lo (9504B) ends 190080
constexpr int PTAIL_OFF = 190080;   // P cols 64,65 fp32 (528B) ends 190608
constexpr int VTH_OFF   = 190608;   // v^T hi: 32 x 72 halfs (4608B)
constexpr int VTL_OFF   = 195216;   // v^T lo (4608B)
constexpr int VTAIL_OFF = 199824;   // V rows 64,65 fp32 (256B) ends 200080
constexpr int PP_OFFB   = 200080;   // pp fp32 66x67 (17688B) ends 217768
constexpr int OO_OFFB   = 200080;   // oo fp32 68x33 overlays pp (PV..cls(next))
constexpr int WC_OFFB   = 217776;   // wc fp32 22x68 (5984B, 16B aligned)
constexpr int BIAS_OFFB = 223760;   // 96 floats
constexpr int SMEM_BYTES = 224144;

constexpr int QS_STRIDE = 33, KT_STRIDE = 68, PP_STRIDE = 67, OO_STRIDE = 33, WC_STRIDE = 68;

typedef unsigned long long ull;

// pre-split weights in global, [h][n][k] layout, scaled x16
__device__ __align__(16) __half g_Wh[8 * 96 * 256];
__device__ __align__(16) __half g_Wl[8 * 96 * 256];

__global__ void repack_weights(const float* __restrict__ Wq,
                               const float* __restrict__ Wk,
                               const float* __restrict__ Wv) {
    int i = blockIdx.x * blockDim.x + threadIdx.x;
    if (i >= 8 * 96 * 256) return;
    int k = i & 255;
    int n = (i >> 8) % 96;
    int h = i / (96 * 256);
    const float* Wsrc = (n < 32) ? Wq : (n < 64 ? Wk : Wv);
    float w = 16.0f * Wsrc[(h * 32 + (n & 31)) * 256 + k];
    __half hi = __float2half_rn(w);
    __half lo = __float2half_rn(w - __half2float(hi));
    g_Wh[i] = hi;
    g_Wl[i] = lo;
}

// ---------------- device helpers ----------------
static __device__ __forceinline__ ull pk2(float a, float b) {
    ull r; asm("mov.b64 %0, {%1,%2};" : "=l"(r) : "f"(a), "f"(b)); return r;
}
static __device__ __forceinline__ void upk2(ull v, float &a, float &b) {
    asm("mov.b64 {%0,%1}, %2;" : "=f"(a), "=f"(b) : "l"(v));
}
static __device__ __forceinline__ ull ffma2(ull a, ull b, ull c) {
    ull d; asm("fma.rn.f32x2 %0, %1, %2, %3;" : "=l"(d) : "l"(a), "l"(b), "l"(c)); return d;
}
static __device__ __forceinline__ void cp16(unsigned dst, const void* src) {
    asm volatile("cp.async.ca.shared.global [%0], [%1], 16;" :: "r"(dst), "l"(src));
}
static __device__ __forceinline__ void cp_commit() { asm volatile("cp.async.commit_group;"); }
static __device__ __forceinline__ void cp_wait0()  { asm volatile("cp.async.wait_group 0;"); }

static __device__ __forceinline__ void mma16816(float* c, const unsigned* a, const unsigned* b) {
    asm volatile("mma.sync.aligned.m16n8k16.row.col.f32.f16.f16.f32 "
        "{%0,%1,%2,%3}, {%4,%5,%6,%7}, {%8,%9}, {%0,%1,%2,%3};"
        : "+f"(c[0]), "+f"(c[1]), "+f"(c[2]), "+f"(c[3])
        : "r"(a[0]), "r"(a[1]), "r"(a[2]), "r"(a[3]), "r"(b[0]), "r"(b[1]));
}

// classifier job: one warp computes out row j for head h (lane = dd)
static __device__ __forceinline__ void cls_job(int j, int lane, const float* wcs,
                                               const float* oo, const float* bc,
                                               float* out, size_t bt, int h) {
    const float4* wr = reinterpret_cast<const float4*>(wcs + j * WC_STRIDE);
    float a = __ldg(bc + j);
    #pragma unroll
    for (int cc = 0; cc < 17; ++cc) {
        float4 w = wr[cc];
        const float* ob = oo + (4 * cc) * OO_STRIDE + lane;
        a += w.x * ob[0] + w.y * ob[OO_STRIDE]
           + w.z * ob[2 * OO_STRIDE] + w.w * ob[3 * OO_STRIDE];
    }
    out[bt * (Jn * 256) + (size_t)h * 32 + (size_t)j * 256 + lane] = a;
}

__global__ __launch_bounds__(NT, 1)
void mha_fused_kernel(const float* __restrict__ x,
                      const float* __restrict__ bq,
                      const float* __restrict__ bk,
                      const float* __restrict__ bv,
                      const float* __restrict__ Wc, const float* __restrict__ bc,
                      float* __restrict__ out)
{
    extern __shared__ float sm[];
    char* smc = reinterpret_cast<char*>(sm);
    float* qs      = reinterpret_cast<float*>(smc + QS_OFFB);
    float* kt      = reinterpret_cast<float*>(smc + KT_OFFB);
    float* oo      = reinterpret_cast<float*>(smc + OO_OFFB);
    float* pp      = reinterpret_cast<float*>(smc + PP_OFFB);
    float* ptail   = reinterpret_cast<float*>(smc + PTAIL_OFF);
    float* vtail   = reinterpret_cast<float*>(smc + VTAIL_OFF);
    float* wcs     = reinterpret_cast<float*>(smc + WC_OFFB);
    float* biasArr = reinterpret_cast<float*>(smc + BIAS_OFFB);

    const size_t bt = blockIdx.x;
    const int tid  = threadIdx.x;
    const int lane = tid & 31;
    const int wid  = tid >> 5;
    const int tm   = lane;

    const unsigned sbase = (unsigned)__cvta_generic_to_shared(smc);

    // ---- prologue: stage W(0) via cp.async ----
    {
        const char* srcH = reinterpret_cast<const char*>(g_Wh);
        const char* srcL = reinterpret_cast<const char*>(g_Wl);
        for (int c = tid; c < 6144; c += NT) {
            int half_sel = c >= 3072;
            int cc = c - (half_sel ? 3072 : 0);
            int n = cc >> 5, ch = cc & 31;
            const char* s = (half_sel ? srcL : srcH) + n * 512 + ch * 16;
            unsigned d = sbase + (half_sel ? WL_OFF : WH_OFF) + n * 528 + ch * 16;
            cp16(d, s);
        }
        cp_commit();
    }
    // ---- x fp32 -> fp16 hi/lo split ----
    {
        const float* xg = x + bt * (Sn * 256);
        for (int t = tid; t < Sn * 256; t += NT) {
            int r = t >> 8, k = t & 255;
            float xv = xg[t];
            __half hi = __float2half_rn(xv);
            __half lo = __float2half_rn(xv - __half2float(hi));
            *reinterpret_cast<__half*>(smc + XH_OFF + r * 528 + k * 2) = hi;
            *reinterpret_cast<__half*>(smc + XL_OFF + r * 528 + k * 2) = lo;
        }
    }
    // ---- wc (+pad cols) ----
    for (int idx = tid; idx < 22 * 68; idx += NT) {
        int j = idx / 68, c = idx - j * 68;
        wcs[idx] = (c < 66) ? Wc[j * 66 + c] : 0.0f;
    }

    const float scale = 0.17677669529663687f; // 1/sqrt(32)

    for (int h = 0; h < Hh; ++h) {
        cp_wait0();                       // W(h) arrived (prefetched during h-1 attention)
        if (tid < 96) {
            const float* bsrc = (tid < 32) ? bq : (tid < 64 ? bk : bv);
            biasArr[tid] = bsrc[h * 32 + (tid & 31)];
        }
        __syncthreads();                  // W(h), bias, and (h>0) oo(h-1) visible

        // ======== phase 1: proj(h) on warps 0-9  ||  cls(h-1) on warps 10-19 ========
        if (wid < 10) {
            // proj job: M16 x N48 -> mt = wid>>1 (0..4), nt = wid&1
            int m0 = (wid >> 1) * 16, n0 = (wid & 1) * 48;
            int g = lane >> 2, kq = (lane & 3) * 2;
            int r0 = m0 + g, r1 = r0 + 8;
            int r0c = (r0 < 66) ? r0 : 65;
            int r1c = (r1 < 66) ? r1 : 65;
            const char* xh0 = smc + XH_OFF + r0c * 528;
            const char* xh1 = smc + XH_OFF + r1c * 528;
            const char* xl0 = smc + XL_OFF + r0c * 528;
            const char* xl1 = smc + XL_OFF + r1c * 528;
            const char* wh[6];
            const char* wl[6];
            #pragma unroll
            for (int s = 0; s < 6; ++s) {
                wh[s] = smc + WH_OFF + (n0 + 8 * s + g) * 528;
                wl[s] = smc + WL_OFF + (n0 + 8 * s + g) * 528;
            }

            float acc[6][4];
            #pragma unroll
            for (int s = 0; s < 6; ++s)
                #pragma unroll
                for (int e = 0; e < 4; ++e) acc[s][e] = 0.0f;

            #pragma unroll
            for (int ks = 0; ks < 16; ++ks) {
                int off = (ks * 16 + kq) * 2;
                unsigned a[4], al[4];
                a[0]  = *reinterpret_cast<const unsigned*>(xh0 + off);
                a[1]  = *reinterpret_cast<const unsigned*>(xh1 + off);
                a[2]  = *reinterpret_cast<const unsigned*>(xh0 + off + 16);
                a[3]  = *reinterpret_cast<const unsigned*>(xh1 + off + 16);
                al[0] = *reinterpret_cast<const unsigned*>(xl0 + off);
                al[1] = *reinterpret_cast<const unsigned*>(xl1 + off);
                al[2] = *reinterpret_cast<const unsigned*>(xl0 + off + 16);
                al[3] = *reinterpret_cast<const unsigned*>(xl1 + off + 16);
                #pragma unroll
                for (int s = 0; s < 6; ++s) {
                    unsigned b[2], bl[2];
                    b[0]  = *reinterpret_cast<const unsigned*>(wh[s] + off);
                    b[1]  = *reinterpret_cast<const unsigned*>(wh[s] + off + 16);
                    bl[0] = *reinterpret_cast<const unsigned*>(wl[s] + off);
                    bl[1] = *reinterpret_cast<const unsigned*>(wl[s] + off + 16);
                    mma16816(acc[s], a, b);
                    mma16816(acc[s], a, bl);
                    mma16816(acc[s], al, b);
                }
            }

            // epilogue: x1/16, +bias; q,k fp32; v fp16 hi/lo (+fp32 tail rows)
            #pragma unroll
            for (int s = 0; s < 6; ++s) {
                int cb = n0 + 8 * s + kq;
                #pragma unroll
                for (int e = 0; e < 2; ++e) {
                    int col = cb + e;
                    float bb = biasArr[col];
                    float v0 = acc[s][e]     * 0.0625f + bb;
                    float v1 = acc[s][2 + e] * 0.0625f + bb;
                    if (col < 32) {
                        if (r0 < 66) qs[r0 * QS_STRIDE + col] = v0;
                        if (r1 < 66) qs[r1 * QS_STRIDE + col] = v1;
                    } else if (col < 64) {
                        if (r0 < 66) kt[(col - 32) * KT_STRIDE + r0] = v0;
                        if (r1 < 66) kt[(col - 32) * KT_STRIDE + r1] = v1;
                    } else {
                        int dd = col - 64;
                        v0 = fmaxf(v0, 0.0f);
                        v1 = fmaxf(v1, 0.0f);
                        if (r0 < 66) {
                            __half h0 = __float2half_rn(v0);
                            __half l0 = __float2half_rn(v0 - __half2float(h0));
                            *reinterpret_cast<__half*>(smc + VTH_OFF + dd * 144 + r0 * 2) = h0;
                            *reinterpret_cast<__half*>(smc + VTL_OFF + dd * 144 + r0 * 2) = l0;
                            if (r0 >= 64) vtail[(r0 - 64) * 32 + dd] = v0;
                        }
                        if (r1 < 66) {
                            __half h1 = __float2half_rn(v1);
                            __half l1 = __float2half_rn(v1 - __half2float(h1));
                            *reinterpret_cast<__half*>(smc + VTH_OFF + dd * 144 + r1 * 2) = h1;
                            *reinterpret_cast<__half*>(smc + VTL_OFF + dd * 144 + r1 * 2) = l1;
                            if (r1 >= 64) vtail[(r1 - 64) * 32 + dd] = v1;
                        }
                    }
                }
            }
        } else if (h > 0) {
            // classifier for head h-1 (oo intact; pp not yet touched this head)
            for (int j = wid - 10; j < Jn; j += 10)
                cls_job(j, lane, wcs, oo, bc, out, bt, h - 1);
        }
        __syncthreads();

        // ---- W(h+1) prefetch: W region dead now; overlaps scores+softmax+PV ----
        if (h + 1 < Hh) {
            const char* srcH = reinterpret_cast<const char*>(g_Wh) + (size_t)(h + 1) * 49152;
            const char* srcL = reinterpret_cast<const char*>(g_Wl) + (size_t)(h + 1) * 49152;
            for (int c = tid; c < 6144; c += NT) {
                int half_sel = c >= 3072;
                int cc = c - (half_sel ? 3072 : 0);
                int n = cc >> 5, ch = cc & 31;
                const char* s = (half_sel ? srcL : srcH) + n * 512 + ch * 16;
                unsigned d = sbase + (half_sel ? WL_OFF : WH_OFF) + n * 528 + ch * 16;
                cp16(d, s);
            }
            cp_commit();
        }

        // ================= scores: 16 warps GEMM + 4 warps cleanup =================
        if (wid < 16) {
            int j0 = wid * 4;
            ull acc[2][2] = {{0ULL, 0ULL}, {0ULL, 0ULL}};
            const float* q0 = qs + tm * QS_STRIDE;
            const float* q1 = qs + (tm + 32) * QS_STRIDE;
            #pragma unroll 8
            for (int d = 0; d < 32; ++d) {
                longlong2 B = *reinterpret_cast<const longlong2*>(kt + d * KT_STRIDE + j0);
                float a0 = q0[d], a1 = q1[d];
                ull u0 = pk2(a0, a0), u1 = pk2(a1, a1);
                acc[0][0] = ffma2(u0, (ull)B.x, acc[0][0]);
                acc[0][1] = ffma2(u0, (ull)B.y, acc[0][1]);
                acc[1][0] = ffma2(u1, (ull)B.x, acc[1][0]);
                acc[1][1] = ffma2(u1, (ull)B.y, acc[1][1]);
            }
            #pragma unroll
            for (int u = 0; u < 2; ++u) {
                int i = tm + 32 * u;
                #pragma unroll
                for (int jp = 0; jp < 2; ++jp) {
                    float s0, s1;
                    upk2(acc[u][jp], s0, s1);
                    int j = j0 + 2 * jp;
                    bool m0 = (i < Jn && j     >= 2 * Jn) || (i >= 2 * Jn && j     < Jn);
                    bool m1 = (i < Jn && j + 1 >= 2 * Jn) || (i >= 2 * Jn && j + 1 < Jn);
                    pp[i * PP_STRIDE + j]     = m0 ? 0.0f : s0 * scale;
                    pp[i * PP_STRIDE + j + 1] = m1 ? 0.0f : s1 * scale;
                }
            }
        } else {
            for (int idx = (wid - 16) * 32 + lane; idx < 260; idx += 128) {
                int i, j;
                if (idx < 132) { i = 64 + idx / 66; j = idx % 66; }
                else { int t2 = idx - 132; i = t2 >> 1; j = 64 + (t2 & 1); }
                bool masked = (i < Jn && j >= 2 * Jn) || (i >= 2 * Jn && j < Jn);
                float s = 0.0f;
                if (!masked) {
                    const float* qi = qs + i * QS_STRIDE;
                    float d0 = 0.0f;
                    #pragma unroll 8
                    for (int d = 0; d < 32; ++d) d0 += qi[d] * kt[d * KT_STRIDE + j];
                    s = d0 * scale;
                }
                pp[i * PP_STRIDE + j] = s;
            }
        }
        __syncthreads();

        // ========== softmax (half-warp per row) + fused fp16 split of P ==========
        {
            const int l16 = lane & 15;
            for (int r = (wid << 1) + (lane >> 4); r < Sn; r += 40) {
                float* row = pp + r * PP_STRIDE;
                float v0 = row[l16];
                float v1 = row[l16 + 16];
                float v2 = row[l16 + 32];
                float v3 = row[l16 + 48];
                float v4 = (l16 < 2) ? row[64 + l16] : -FLT_MAX;
                float m = fmaxf(fmaxf(fmaxf(v0, v1), fmaxf(v2, v3)), v4);
                #pragma unroll
                for (int o = 8; o; o >>= 1) m = fmaxf(m, __shfl_xor_sync(0xffffffffu, m, o, 16));
                float thr = m * (1.0f / 9.0f);
                float t0 = (fabsf(v0) <= thr) ? NEGV : v0;
                float t1 = (fabsf(v1) <= thr) ? NEGV : v1;
                float t2 = (fabsf(v2) <= thr) ? NEGV : v2;
                float t3 = (fabsf(v3) <= thr) ? NEGV : v3;
                float t4 = (l16 < 2) ? ((fabsf(v4) <= thr) ? NEGV : v4) : -FLT_MAX;
                float M2 = fmaxf(fmaxf(fmaxf(t0, t1), fmaxf(t2, t3)), t4);
                #pragma unroll
                for (int o = 8; o; o >>= 1) M2 = fmaxf(M2, __shfl_xor_sync(0xffffffffu, M2, o, 16));
                float e0 = __expf(t0 - M2);
                float e1 = __expf(t1 - M2);
                float e2 = __expf(t2 - M2);
                float e3 = __expf(t3 - M2);
                float e4 = (l16 < 2) ? __expf(t4 - M2) : 0.0f;
                float s = e0 + e1 + e2 + e3 + e4;
                #pragma unroll
                for (int o = 8; o; o >>= 1) s += __shfl_xor_sync(0xffffffffu, s, o, 16);
                float inv = 1.0f / s;
                char* phr = smc + PH_OFF + r * 144;
                char* plr = smc + PL_OFF + r * 144;
                #pragma unroll
                for (int q = 0; q < 4; ++q) {
                    float p = (q == 0 ? e0 : q == 1 ? e1 : q == 2 ? e2 : e3) * inv;
                    int c = l16 + 16 * q;
                    __half hp = __float2half_rn(p);
                    __half lp = __float2half_rn(p - __half2float(hp));
                    *reinterpret_cast<__half*>(phr + c * 2) = hp;
                    *reinterpret_cast<__half*>(plr + c * 2) = lp;
                }
                if (l16 < 2) {
                    float p = e4 * inv;
                    int c = 64 + l16;
                    __half hp = __float2half_rn(p);
                    __half lp = __float2half_rn(p - __half2float(hp));
                    *reinterpret_cast<__half*>(phr + c * 2) = hp;
                    *reinterpret_cast<__half*>(plr + c * 2) = lp;
                    ptail[r * 2 + l16] = p;
                }
            }
        }
        __syncthreads();

        // ================= P @ V via HMMA: one job per warp =================
        if (wid < 20) {
            int mt = wid >> 2, nt = wid & 3;
            int m0 = mt * 16, n0 = nt * 8;
            int g = lane >> 2, kq = (lane & 3) * 2;
            int r0 = m0 + g, r1 = r0 + 8;
            int r0c = (r0 < 66) ? r0 : 65;
            int r1c = (r1 < 66) ? r1 : 65;
            const char* ah0 = smc + PH_OFF + r0c * 144;
            const char* ah1 = smc + PH_OFF + r1c * 144;
            const char* al0 = smc + PL_OFF + r0c * 144;
            const char* al1 = smc + PL_OFF + r1c * 144;
            const char* bh  = smc + VTH_OFF + (n0 + g) * 144;
            const char* blp = smc + VTL_OFF + (n0 + g) * 144;

            float acc[4] = {0.0f, 0.0f, 0.0f, 0.0f};
            #pragma unroll
            for (int ks = 0; ks < 4; ++ks) {
                int off = (ks * 16 + kq) * 2;
                unsigned a[4], al[4], b[2], bl[2];
                a[0]  = *reinterpret_cast<const unsigned*>(ah0 + off);
                a[1]  = *reinterpret_cast<const unsigned*>(ah1 + off);
                a[2]  = *reinterpret_cast<const unsigned*>(ah0 + off + 16);
                a[3]  = *reinterpret_cast<const unsigned*>(ah1 + off + 16);
                al[0] = *reinterpret_cast<const unsigned*>(al0 + off);
                al[1] = *reinterpret_cast<const unsigned*>(al1 + off);
                al[2] = *reinterpret_cast<const unsigned*>(al0 + off + 16);
                al[3] = *reinterpret_cast<const unsigned*>(al1 + off + 16);
                b[0]  = *reinterpret_cast<const unsigned*>(bh + off);
                b[1]  = *reinterpret_cast<const unsigned*>(bh + off + 16);
                bl[0] = *reinterpret_cast<const unsigned*>(blp + off);
                bl[1] = *reinterpret_cast<const unsigned*>(blp + off + 16);
                mma16816(acc, a, b);
                mma16816(acc, a, bl);
                mma16816(acc, al, b);
            }
            // fp32 tail k = 64,65
            float p64_0 = ptail[r0c * 2], p65_0 = ptail[r0c * 2 + 1];
            float p64_1 = ptail[r1c * 2], p65_1 = ptail[r1c * 2 + 1];
            #pragma unroll
            for (int e = 0; e < 2; ++e) {
                int dd = n0 + kq + e;
                float vt64 = vtail[dd], vt65 = vtail[32 + dd];
                float c0 = acc[e]     + p64_0 * vt64 + p65_0 * vt65;
                float c1 = acc[2 + e] + p64_1 * vt64 + p65_1 * vt65;
                if (r0 < 66) oo[r0 * OO_STRIDE + dd] = c0;
                if (r1 < 66) oo[r1 * OO_STRIDE + dd] = c1;
            }
        }
        // oo pad rows 66,67 (pp overlay clobbers them each head)
        if (tid < 66) oo[66 * OO_STRIDE + tid] = 0.0f;
        __syncthreads();
    }

    // final classifier for head 7 (all warps)
    for (int j = wid; j < Jn; j += 20)
        cls_job(j, lane, wcs, oo, bc, out, bt, Hh - 1);
}

extern "C" void kernel_launch(void* const* d_in, const int* in_sizes, int n_in,
                              void* d_out, int out_size) {
    const float* x  = (const float*)d_in[0];
    const float* Wq = (const float*)d_in[1];
    const float* bq = (const float*)d_in[2];
    const float* Wk = (const float*)d_in[3];
    const float* bk = (const float*)d_in[4];
    const float* Wv = (const float*)d_in[5];
    const float* bv = (const float*)d_in[6];
    const float* Wc = (const float*)d_in[7];
    const float* bc = (const float*)d_in[8];
    float* out = (float*)d_out;

    repack_weights<<<(8 * 96 * 256 + 255) / 256, 256>>>(Wq, Wk, Wv);

    int blocks = in_sizes[0] / (Sn * 256);   // B*T = 3072
    cudaFuncSetAttribute(mha_fused_kernel,
                         cudaFuncAttributeMaxDynamicSharedMemorySize, SMEM_BYTES);
    mha_fused_kernel<<<blocks, NT, SMEM_BYTES>>>(x, bq, bk, bv, Wc, bc, out);
}

// round 14
// speedup vs baseline: 1.4084x; 1.1276x over previous
#include <cuda_runtime.h>
#include <cuda_fp16.h>
#include <cstdint>
#include <math.h>
#include <float.h>

constexpr int Hh = 8;
constexpr int Jn = 22;
constexpr int Sn = 66;
constexpr int NT = 640;   // 20 warps: 0-9 proj (P), 10-19 attention (C)
#define NEGV (-9e15f)

// ---------------- smem byte layout (same regions as R13) ----------------
constexpr int XH_OFF    = 0;        // x hi: 66 x 264 halfs
constexpr int XL_OFF    = 34848;    // x lo
constexpr int WH_OFF    = 69696;    // W hi
constexpr int WL_OFF    = 120384;   // W lo, ends 171072
constexpr int QS_OFFB   = 171072;   // qs fp32 66x33
constexpr int KT_OFFB   = 179792;   // kt fp32 32x68 (16B aligned), ends 188496
constexpr int PH_OFF    = 171072;   // P hi overlays qs/kt (live softmax..PV)
constexpr int PL_OFF    = 180576;
constexpr int PTAIL_OFF = 190080;   // ends 190608
constexpr int VTH_OFF   = 190608;   // v^T hi 32x72 halfs
constexpr int VTL_OFF   = 195216;
constexpr int VTAIL_OFF = 199824;   // ends 200080
constexpr int PP_OFFB   = 200080;   // pp fp32 66x67
constexpr int OO_OFFB   = 200080;   // oo overlays pp (live PV..cls)
constexpr int WC_OFFB   = 217776;   // wc fp32 22x68
constexpr int SMEM_BYTES = 223760;

constexpr int QS_STRIDE = 33, KT_STRIDE = 68, PP_STRIDE = 67, OO_STRIDE = 33, WC_STRIDE = 68;

typedef unsigned long long ull;

__device__ __align__(16) __half g_Wh[8 * 96 * 256];
__device__ __align__(16) __half g_Wl[8 * 96 * 256];

__global__ void repack_weights(const float* __restrict__ Wq,
                               const float* __restrict__ Wk,
                               const float* __restrict__ Wv) {
    int i = blockIdx.x * blockDim.x + threadIdx.x;
    if (i >= 8 * 96 * 256) return;
    int k = i & 255;
    int n = (i >> 8) % 96;
    int h = i / (96 * 256);
    const float* Wsrc = (n < 32) ? Wq : (n < 64 ? Wk : Wv);
    float w = 16.0f * Wsrc[(h * 32 + (n & 31)) * 256 + k];
    __half hi = __float2half_rn(w);
    __half lo = __float2half_rn(w - __half2float(hi));
    g_Wh[i] = hi;
    g_Wl[i] = lo;
}

// ---------------- helpers ----------------
static __device__ __forceinline__ ull pk2(float a, float b) {
    ull r; asm("mov.b64 %0, {%1,%2};" : "=l"(r) : "f"(a), "f"(b)); return r;
}
static __device__ __forceinline__ void upk2(ull v, float &a, float &b) {
    asm("mov.b64 {%0,%1}, %2;" : "=f"(a), "=f"(b) : "l"(v));
}
static __device__ __forceinline__ ull ffma2(ull a, ull b, ull c) {
    ull d; asm("fma.rn.f32x2 %0, %1, %2, %3;" : "=l"(d) : "l"(a), "l"(b), "l"(c)); return d;
}
static __device__ __forceinline__ void cp16(unsigned dst, const void* src) {
    asm volatile("cp.async.ca.shared.global [%0], [%1], 16;" :: "r"(dst), "l"(src));
}
static __device__ __forceinline__ void cp_commit() { asm volatile("cp.async.commit_group;"); }
static __device__ __forceinline__ void cp_wait0()  { asm volatile("cp.async.wait_group 0;"); }

#define BAR_C()         asm volatile("bar.sync 1, 320;" ::: "memory")
#define BAR_PV_ARRIVE() asm volatile("bar.arrive 2, 640;" ::: "memory")
#define BAR_PV_WAIT()   asm volatile("bar.sync 2, 640;" ::: "memory")
#define BAR_P()         asm volatile("bar.sync 3, 320;" ::: "memory")

static __device__ __forceinline__ void mma16816(float* c, const unsigned* a, const unsigned* b) {
    asm volatile("mma.sync.aligned.m16n8k16.row.col.f32.f16.f16.f32 "
        "{%0,%1,%2,%3}, {%4,%5,%6,%7}, {%8,%9}, {%0,%1,%2,%3};"
        : "+f"(c[0]), "+f"(c[1]), "+f"(c[2]), "+f"(c[3])
        : "r"(a[0]), "r"(a[1]), "r"(a[2]), "r"(a[3]), "r"(b[0]), "r"(b[1]));
}

// ---- proj MMA (group P, one M16xN48 job per warp, wid 0..9) ----
static __device__ __forceinline__ void proj_mma(const char* smc, int wid, int lane,
                                                float acc[6][4]) {
    int m0 = (wid >> 1) * 16, n0 = (wid & 1) * 48;
    int g = lane >> 2, kq = (lane & 3) * 2;
    int r0 = m0 + g, r1 = r0 + 8;
    int r0c = (r0 < 66) ? r0 : 65;
    int r1c = (r1 < 66) ? r1 : 65;
    const char* xh0 = smc + XH_OFF + r0c * 528;
    const char* xh1 = smc + XH_OFF + r1c * 528;
    const char* xl0 = smc + XL_OFF + r0c * 528;
    const char* xl1 = smc + XL_OFF + r1c * 528;
    const char* whb = smc + WH_OFF + (n0 + g) * 528;
    const char* wlb = smc + WL_OFF + (n0 + g) * 528;

    #pragma unroll
    for (int s = 0; s < 6; ++s)
        #pragma unroll
        for (int e = 0; e < 4; ++e) acc[s][e] = 0.0f;

    #pragma unroll
    for (int ks = 0; ks < 16; ++ks) {
        int off = (ks * 16 + kq) * 2;
        unsigned a[4], al[4];
        a[0]  = *reinterpret_cast<const unsigned*>(xh0 + off);
        a[1]  = *reinterpret_cast<const unsigned*>(xh1 + off);
        a[2]  = *reinterpret_cast<const unsigned*>(xh0 + off + 16);
        a[3]  = *reinterpret_cast<const unsigned*>(xh1 + off + 16);
        al[0] = *reinterpret_cast<const unsigned*>(xl0 + off);
        al[1] = *reinterpret_cast<const unsigned*>(xl1 + off);
        al[2] = *reinterpret_cast<const unsigned*>(xl0 + off + 16);
        al[3] = *reinterpret_cast<const unsigned*>(xl1 + off + 16);
        #pragma unroll
        for (int s = 0; s < 6; ++s) {
            unsigned b[2], bl[2];
            b[0]  = *reinterpret_cast<const unsigned*>(whb + s * 8 * 528 + off);
            b[1]  = *reinterpret_cast<const unsigned*>(whb + s * 8 * 528 + off + 16);
            bl[0] = *reinterpret_cast<const unsigned*>(wlb + s * 8 * 528 + off);
            bl[1] = *reinterpret_cast<const unsigned*>(wlb + s * 8 * 528 + off + 16);
            mma16816(acc[s], a, b);
            mma16816(acc[s], a, bl);
            mma16816(acc[s], al, b);
        }
    }
}

// ---- proj epilogue: x1/16 + bias (direct ldg); q,k fp32; v fp16 hi/lo + tail ----
static __device__ __forceinline__ void proj_epilogue(char* smc, int wid, int lane, int h,
        float acc[6][4],
        const float* __restrict__ bq, const float* __restrict__ bk,
        const float* __restrict__ bv) {
    float* qs    = reinterpret_cast<float*>(smc + QS_OFFB);
    float* kt    = reinterpret_cast<float*>(smc + KT_OFFB);
    float* vtail = reinterpret_cast<float*>(smc + VTAIL_OFF);
    int m0 = (wid >> 1) * 16, n0 = (wid & 1) * 48;
    int g = lane >> 2, kq = (lane & 3) * 2;
    int r0 = m0 + g, r1 = r0 + 8;
    #pragma unroll
    for (int s = 0; s < 6; ++s) {
        int cb = n0 + 8 * s + kq;
        #pragma unroll
        for (int e = 0; e < 2; ++e) {
            int col = cb + e;
            const float* bsrc = (col < 32) ? bq : (col < 64 ? bk : bv);
            float bb = __ldg(bsrc + h * 32 + (col & 31));
            float v0 = acc[s][e]     * 0.0625f + bb;
            float v1 = acc[s][2 + e] * 0.0625f + bb;
            if (col < 32) {
                if (r0 < 66) qs[r0 * QS_STRIDE + col] = v0;
                if (r1 < 66) qs[r1 * QS_STRIDE + col] = v1;
            } else if (col < 64) {
                if (r0 < 66) kt[(col - 32) * KT_STRIDE + r0] = v0;
                if (r1 < 66) kt[(col - 32) * KT_STRIDE + r1] = v1;
            } else {
                int dd = col - 64;
                v0 = fmaxf(v0, 0.0f);
                v1 = fmaxf(v1, 0.0f);
                if (r0 < 66) {
                    __half h0 = __float2half_rn(v0);
                    __half l0 = __float2half_rn(v0 - __half2float(h0));
                    *reinterpret_cast<__half*>(smc + VTH_OFF + dd * 144 + r0 * 2) = h0;
                    *reinterpret_cast<__half*>(smc + VTL_OFF + dd * 144 + r0 * 2) = l0;
                    if (r0 >= 64) vtail[(r0 - 64) * 32 + dd] = v0;
                }
                if (r1 < 66) {
                    __half h1 = __float2half_rn(v1);
                    __half l1 = __float2half_rn(v1 - __half2float(h1));
                    *reinterpret_cast<__half*>(smc + VTH_OFF + dd * 144 + r1 * 2) = h1;
                    *reinterpret_cast<__half*>(smc + VTL_OFF + dd * 144 + r1 * 2) = l1;
                    if (r1 >= 64) vtail[(r1 - 64) * 32 + dd] = v1;
                }
            }
        }
    }
}

// ---- W prefetch: issued by group P threads only (tid 0..319) ----
static __device__ __forceinline__ void issue_W(unsigned sbase, int tid, int h) {
    const char* srcH = reinterpret_cast<const char*>(g_Wh) + (size_t)h * 49152;
    const char* srcL = reinterpret_cast<const char*>(g_Wl) + (size_t)h * 49152;
    for (int c = tid; c < 6144; c += 320) {
        int half_sel = c >= 3072;
        int cc = c - (half_sel ? 3072 : 0);
        int n = cc >> 5, ch = cc & 31;
        const char* s = (half_sel ? srcL : srcH) + n * 512 + ch * 16;
        unsigned d = sbase + (half_sel ? WL_OFF : WH_OFF) + n * 528 + ch * 16;
        cp16(d, s);
    }
    cp_commit();
}

// ---- classifier job ----
static __device__ __forceinline__ void cls_job(int j, int lane, const float* wcs,
                                               const float* oo, const float* bc,
                                               float* out, size_t bt, int h) {
    const float4* wr = reinterpret_cast<const float4*>(wcs + j * WC_STRIDE);
    float a = __ldg(bc + j);
    #pragma unroll
    for (int cc = 0; cc < 17; ++cc) {
        float4 w = wr[cc];
        const float* ob = oo + (4 * cc) * OO_STRIDE + lane;
        a += w.x * ob[0] + w.y * ob[OO_STRIDE]
           + w.z * ob[2 * OO_STRIDE] + w.w * ob[3 * OO_STRIDE];
    }
    out[bt * (Jn * 256) + (size_t)h * 32 + (size_t)j * 256 + lane] = a;
}

__global__ __launch_bounds__(NT, 1)
void mha_fused_kernel(const float* __restrict__ x,
                      const float* __restrict__ bq,
                      const float* __restrict__ bk,
                      const float* __restrict__ bv,
                      const float* __restrict__ Wc, const float* __restrict__ bc,
                      float* __restrict__ out)
{
    extern __shared__ float sm[];
    char* smc = reinterpret_cast<char*>(sm);
    float* qs    = reinterpret_cast<float*>(smc + QS_OFFB);
    float* kt    = reinterpret_cast<float*>(smc + KT_OFFB);
    float* oo    = reinterpret_cast<float*>(smc + OO_OFFB);
    float* pp    = reinterpret_cast<float*>(smc + PP_OFFB);
    float* ptail = reinterpret_cast<float*>(smc + PTAIL_OFF);
    float* vtail = reinterpret_cast<float*>(smc + VTAIL_OFF);
    float* wcs   = reinterpret_cast<float*>(smc + WC_OFFB);

    const size_t bt = blockIdx.x;
    const int tid  = threadIdx.x;
    const int lane = tid & 31;
    const int wid  = tid >> 5;

    const unsigned sbase = (unsigned)__cvta_generic_to_shared(smc);
    const float scale = 0.17677669529663687f; // 1/sqrt(32)

    // ================= prologue =================
    if (wid < 10) issue_W(sbase, tid, 0);

    {   // x fp32 -> fp16 hi/lo split (all threads)
        const float* xg = x + bt * (Sn * 256);
        for (int t = tid; t < Sn * 256; t += NT) {
            int r = t >> 8, k = t & 255;
            float xv = xg[t];
            __half hi = __float2half_rn(xv);
            __half lo = __float2half_rn(xv - __half2float(hi));
            *reinterpret_cast<__half*>(smc + XH_OFF + r * 528 + k * 2) = hi;
            *reinterpret_cast<__half*>(smc + XL_OFF + r * 528 + k * 2) = lo;
        }
    }
    for (int idx = tid; idx < 22 * 68; idx += NT) {
        int j = idx / 68, c = idx - j * 68;
        wcs[idx] = (c < 66) ? Wc[j * 66 + c] : 0.0f;
    }
    __syncthreads();   // x, wcs visible

    if (wid < 10) {
        cp_wait0();
        BAR_P();       // W(0) visible across group P
        float acc[6][4];
        proj_mma(smc, wid, lane, acc);
        proj_epilogue(smc, wid, lane, 0, acc, bq, bk, bv);
        issue_W(sbase, tid, 1);
    }
    __syncthreads();   // qkv(0) visible to group C

    // ================= pipelined loop =================
    for (int h = 0; h < Hh; ++h) {
        if (wid < 10) {
            // -------- group P: proj(h+1) --------
            if (h < 7) {
                cp_wait0();
                BAR_P();   // W(h+1) visible across group P
                float acc[6][4];
                proj_mma(smc, wid, lane, acc);
                BAR_PV_WAIT();   // wait until PV(h) finished reading P/vt regions
                proj_epilogue(smc, wid, lane, h + 1, acc, bq, bk, bv);
                if (h + 2 < Hh) issue_W(sbase, tid, h + 2);
            } else {
                BAR_PV_WAIT();
            }
        } else {
            // -------- group C: attention(h) --------
            const int cw = wid - 10;   // 0..9

            // scores: warps 0..8 -> 8 cols each; warp 9 -> rows 64,65 cleanup
            if (cw < 9) {
                int j0 = cw * 8;
                ull acc[2][4];
                #pragma unroll
                for (int u = 0; u < 2; ++u)
                    #pragma unroll
                    for (int jp = 0; jp < 4; ++jp) acc[u][jp] = 0ULL;
                const float* q0 = qs + lane * QS_STRIDE;
                const float* q1 = qs + (lane + 32) * QS_STRIDE;
                #pragma unroll 8
                for (int d = 0; d < 32; ++d) {
                    const float* kr = kt + d * KT_STRIDE + j0;
                    longlong2 B0 = *reinterpret_cast<const longlong2*>(kr);
                    longlong2 B1 = *reinterpret_cast<const longlong2*>(kr + 4);
                    float a0 = q0[d], a1 = q1[d];
                    ull u0 = pk2(a0, a0), u1 = pk2(a1, a1);
                    acc[0][0] = ffma2(u0, (ull)B0.x, acc[0][0]);
                    acc[0][1] = ffma2(u0, (ull)B0.y, acc[0][1]);
                    acc[0][2] = ffma2(u0, (ull)B1.x, acc[0][2]);
                    acc[0][3] = ffma2(u0, (ull)B1.y, acc[0][3]);
                    acc[1][0] = ffma2(u1, (ull)B0.x, acc[1][0]);
                    acc[1][1] = ffma2(u1, (ull)B0.y, acc[1][1]);
                    acc[1][2] = ffma2(u1, (ull)B1.x, acc[1][2]);
                    acc[1][3] = ffma2(u1, (ull)B1.y, acc[1][3]);
                }
                #pragma unroll
                for (int u = 0; u < 2; ++u) {
                    int i = lane + 32 * u;
                    #pragma unroll
                    for (int jp = 0; jp < 4; ++jp) {
                        float s0, s1;
                        upk2(acc[u][jp], s0, s1);
                        int j = j0 + 2 * jp;
                        if (j < 66) {
                            bool m0 = (i < Jn && j >= 2 * Jn) || (i >= 2 * Jn && j < Jn);
                            pp[i * PP_STRIDE + j] = m0 ? 0.0f : s0 * scale;
                        }
                        if (j + 1 < 66) {
                            bool m1 = (i < Jn && j + 1 >= 2 * Jn) || (i >= 2 * Jn && j + 1 < Jn);
                            pp[i * PP_STRIDE + j + 1] = m1 ? 0.0f : s1 * scale;
                        }
                    }
                }
            } else {
                for (int idx = lane; idx < 132; idx += 32) {
                    int i = 64 + (idx >= 66);
                    int j = (idx >= 66) ? (idx - 66) : idx;
                    bool masked = (i < Jn && j >= 2 * Jn) || (i >= 2 * Jn && j < Jn);
                    float s = 0.0f;
                    if (!masked) {
                        const float* qi = qs + i * QS_STRIDE;
                        float d0 = 0.0f;
                        #pragma unroll 8
                        for (int d = 0; d < 32; ++d) d0 += qi[d] * kt[d * KT_STRIDE + j];
                        s = d0 * scale;
                    }
                    pp[i * PP_STRIDE + j] = s;
                }
            }
            BAR_C();

            // softmax + fused fp16 split of P (20 half-warps)
            {
                const int l16 = lane & 15;
                for (int r = (cw << 1) + (lane >> 4); r < Sn; r += 20) {
                    float* row = pp + r * PP_STRIDE;
                    float v0 = row[l16];
                    float v1 = row[l16 + 16];
                    float v2 = row[l16 + 32];
                    float v3 = row[l16 + 48];
                    float v4 = (l16 < 2) ? row[64 + l16] : -FLT_MAX;
                    float m = fmaxf(fmaxf(fmaxf(v0, v1), fmaxf(v2, v3)), v4);
                    #pragma unroll
                    for (int o = 8; o; o >>= 1) m = fmaxf(m, __shfl_xor_sync(0xffffffffu, m, o, 16));
                    float thr = m * (1.0f / 9.0f);
                    float t0 = (fabsf(v0) <= thr) ? NEGV : v0;
                    float t1 = (fabsf(v1) <= thr) ? NEGV : v1;
                    float t2 = (fabsf(v2) <= thr) ? NEGV : v2;
                    float t3 = (fabsf(v3) <= thr) ? NEGV : v3;
                    float t4 = (l16 < 2) ? ((fabsf(v4) <= thr) ? NEGV : v4) : -FLT_MAX;
                    float M2 = fmaxf(fmaxf(fmaxf(t0, t1), fmaxf(t2, t3)), t4);
                    #pragma unroll
                    for (int o = 8; o; o >>= 1) M2 = fmaxf(M2, __shfl_xor_sync(0xffffffffu, M2, o, 16));
                    float e0 = __expf(t0 - M2);
                    float e1 = __expf(t1 - M2);
                    float e2 = __expf(t2 - M2);
                    float e3 = __expf(t3 - M2);
                    float e4 = (l16 < 2) ? __expf(t4 - M2) : 0.0f;
                    float s = e0 + e1 + e2 + e3 + e4;
                    #pragma unroll
                    for (int o = 8; o; o >>= 1) s += __shfl_xor_sync(0xffffffffu, s, o, 16);
                    float inv = 1.0f / s;
                    char* phr = smc + PH_OFF + r * 144;
                    char* plr = smc + PL_OFF + r * 144;
                    #pragma unroll
                    for (int q = 0; q < 4; ++q) {
                        float p = (q == 0 ? e0 : q == 1 ? e1 : q == 2 ? e2 : e3) * inv;
                        int c = l16 + 16 * q;
                        __half hp = __float2half_rn(p);
                        __half lp = __float2half_rn(p - __half2float(hp));
                        *reinterpret_cast<__half*>(phr + c * 2) = hp;
                        *reinterpret_cast<__half*>(plr + c * 2) = lp;
                    }
                    if (l16 < 2) {
                        float p = e4 * inv;
                        int c = 64 + l16;
                        __half hp = __float2half_rn(p);
                        __half lp = __float2half_rn(p - __half2float(hp));
                        *reinterpret_cast<__half*>(phr + c * 2) = hp;
                        *reinterpret_cast<__half*>(plr + c * 2) = lp;
                        ptail[r * 2 + l16] = p;
                    }
                }
            }
            BAR_C();

            // P @ V via HMMA: 10 jobs M16 x N16
            {
                int mt = cw >> 1, nt = cw & 1;
                int m0 = mt * 16, n0 = nt * 16;
                int g = lane >> 2, kq = (lane & 3) * 2;
                int r0 = m0 + g, r1 = r0 + 8;
                int r0c = (r0 < 66) ? r0 : 65;
                int r1c = (r1 < 66) ? r1 : 65;
                const char* ah0 = smc + PH_OFF + r0c * 144;
                const char* ah1 = smc + PH_OFF + r1c * 144;
                const char* al0 = smc + PL_OFF + r0c * 144;
                const char* al1 = smc + PL_OFF + r1c * 144;
                const char* bh0 = smc + VTH_OFF + (n0 + g) * 144;
                const char* bh1 = bh0 + 8 * 144;
                const char* bl0 = smc + VTL_OFF + (n0 + g) * 144;
                const char* bl1 = bl0 + 8 * 144;

                float acc[2][4];
                #pragma unroll
                for (int f = 0; f < 2; ++f)
                    #pragma unroll
                    for (int e = 0; e < 4; ++e) acc[f][e] = 0.0f;

                #pragma unroll
                for (int ks = 0; ks < 4; ++ks) {
                    int off = (ks * 16 + kq) * 2;
                    unsigned a[4], al[4];
                    a[0]  = *reinterpret_cast<const unsigned*>(ah0 + off);
                    a[1]  = *reinterpret_cast<const unsigned*>(ah1 + off);
                    a[2]  = *reinterpret_cast<const unsigned*>(ah0 + off + 16);
                    a[3]  = *reinterpret_cast<const unsigned*>(ah1 + off + 16);
                    al[0] = *reinterpret_cast<const unsigned*>(al0 + off);
                    al[1] = *reinterpret_cast<const unsigned*>(al1 + off);
                    al[2] = *reinterpret_cast<const unsigned*>(al0 + off + 16);
                    al[3] = *reinterpret_cast<const unsigned*>(al1 + off + 16);
                    unsigned b[2], bl[2];
                    b[0]  = *reinterpret_cast<const unsigned*>(bh0 + off);
                    b[1]  = *reinterpret_cast<const unsigned*>(bh0 + off + 16);
                    bl[0] = *reinterpret_cast<const unsigned*>(bl0 + off);
                    bl[1] = *reinterpret_cast<const unsigned*>(bl0 + off + 16);
                    mma16816(acc[0], a, b);
                    mma16816(acc[0], a, bl);
                    mma16816(acc[0], al, b);
                    b[0]  = *reinterpret_cast<const unsigned*>(bh1 + off);
                    b[1]  = *reinterpret_cast<const unsigned*>(bh1 + off + 16);
                    bl[0] = *reinterpret_cast<const unsigned*>(bl1 + off);
                    bl[1] = *reinterpret_cast<const unsigned*>(bl1 + off + 16);
                    mma16816(acc[1], a, b);
                    mma16816(acc[1], a, bl);
                    mma16816(acc[1], al, b);
                }
                float p64_0 = ptail[r0c * 2], p65_0 = ptail[r0c * 2 + 1];
                float p64_1 = ptail[r1c * 2], p65_1 = ptail[r1c * 2 + 1];
                #pragma unroll
                for (int f = 0; f < 2; ++f) {
                    #pragma unroll
                    for (int e = 0; e < 2; ++e) {
                        int dd = n0 + 8 * f + kq + e;
                        float vt64 = vtail[dd], vt65 = vtail[32 + dd];
                        float c0 = acc[f][e]     + p64_0 * vt64 + p65_0 * vt65;
                        float c1 = acc[f][2 + e] + p64_1 * vt64 + p65_1 * vt65;
                        if (r0 < 66) oo[r0 * OO_STRIDE + dd] = c0;
                        if (r1 < 66) oo[r1 * OO_STRIDE + dd] = c1;
                    }
                }
            }
            BAR_PV_ARRIVE();   // P/vt reads done -> proj epilogue may overwrite

            // oo pad rows (overwritten by scores/pp each head)
            {
                int ct = tid - 320;
                if (ct < 66) oo[66 * OO_STRIDE + ct] = 0.0f;
            }
            BAR_C();

            // classifier for head h
            for (int j = cw; j < Jn; j += 10)
                cls_job(j, lane, wcs, oo, bc, out, bt, h);
        }
        __syncthreads();   // epilogue(h+1) + cls(h) complete
    }
}

extern "C" void kernel_launch(void* const* d_in, const int* in_sizes, int n_in,
                              void* d_out, int out_size) {
    const float* x  = (const float*)d_in[0];
    const float* Wq = (const float*)d_in[1];
    const float* bq = (const float*)d_in[2];
    const float* Wk = (const float*)d_in[3];
    const float* bk = (const float*)d_in[4];
    const float* Wv = (const float*)d_in[5];
    const float* bv = (const float*)d_in[6];
    const float* Wc = (const float*)d_in[7];
    const float* bc = (const float*)d_in[8];
    float* out = (float*)d_out;

    repack_weights<<<(8 * 96 * 256 + 255) / 256, 256>>>(Wq, Wk, Wv);

    int blocks = in_sizes[0] / (Sn * 256);   // B*T = 3072
    cudaFuncSetAttribute(mha_fused_kernel,
                         cudaFuncAttributeMaxDynamicSharedMemorySize, SMEM_BYTES);
    mha_fused_kernel<<<blocks, NT, SMEM_BYTES>>>(x, bq, bk, bv, Wc, bc, out);
}